// round 10
// baseline (speedup 1.0000x reference)
#include <cuda_runtime.h>

typedef unsigned long long ull;

// ---------------- packed f32x2 helpers (sm_103a) ----------------
__device__ __forceinline__ ull f2mul(ull a, ull b) {
    ull d; asm("mul.rn.f32x2 %0,%1,%2;" : "=l"(d) : "l"(a), "l"(b)); return d;
}
__device__ __forceinline__ ull f2fma(ull a, ull b, ull c) {
    ull d; asm("fma.rn.f32x2 %0,%1,%2,%3;" : "=l"(d) : "l"(a), "l"(b), "l"(c)); return d;
}
__device__ __forceinline__ ull f2add(ull a, ull b) {
    ull d; asm("add.rn.f32x2 %0,%1,%2;" : "=l"(d) : "l"(a), "l"(b)); return d;
}
__device__ __forceinline__ void f2unpack(ull v, float& lo, float& hi) {
    asm("mov.b64 {%0,%1},%2;" : "=f"(lo), "=f"(hi) : "l"(v));
}
__device__ __forceinline__ ull f2pack(float v) {
    ull d; asm("mov.b64 %0,{%1,%1};" : "=l"(d) : "f"(v)); return d;
}
__device__ __forceinline__ ull f2pack2(float a, float b) {
    ull d; asm("mov.b64 %0,{%1,%2};" : "=l"(d) : "f"(a), "f"(b)); return d;
}

// parity-preserving padded index for the packed-u array: +2 gap at >=48 and
// >=96 kills the 384B-periodicity bank conflict while keeping even indices
// 16B-aligned (required for the paired LDS.128 loads).
__device__ __forceinline__ int padidx2(int p) {
    return p + 2 * (p >= 48) + 2 * (p >= 96);
}

// ---------------- scratch (no allocations allowed) ----------------
__device__ float g_feat[16384 * 192];
__device__ float g_ce[8192 * 576];
__device__ float g_h[8192 * 288];

__device__ __forceinline__ float lrelu_f(float v) { return v >= 0.f ? v : 0.1f * v; }

// dummy no-op kernel: shifts the ncu capture slot onto k1_fusion
__global__ void k_nop() {}

// =====================================================================
// K1 (fused): per (row, half) fusion features.
// Hot loop processes 2 rows per step with one LDS.128 per tt channel
// (u stored duplicated {u,u}; pair = {u[p],u[p],u[p+1],u[p+1]}).
// =====================================================================
__global__ __launch_bounds__(192, 5) void k1_fusion(
    const float* __restrict__ x,
    const float* __restrict__ cw1, const float* __restrict__ cb1,
    const float* __restrict__ cw2, const float* __restrict__ cb2,
    const float* __restrict__ cw3, const float* __restrict__ cb3,
    const float* __restrict__ cw4, const float* __restrict__ cb4,
    const float* __restrict__ cw5, const float* __restrict__ cb5,
    const float* __restrict__ cw6, const float* __restrict__ cb6,
    const float* __restrict__ de_W, const float* __restrict__ de_b,
    float* __restrict__ gfeat)
{
    int r = blockIdx.x;
    int h = blockIdx.y;
    int t = threadIdx.x;
    int warp = t >> 5, lane = t & 31;

    __shared__ float sin_[288];
    __shared__ float t1[288];
    __shared__ float abuf[3][96];
    __shared__ __align__(16) float vpad[3][98];
    __shared__ __align__(16) ull u2p[3][104];    // duplicated padded rows, parity-preserving pad
    __shared__ __align__(16) float wv[9][96];
    __shared__ float kersh[9];
    __shared__ float sWV[9];
    __shared__ float Ssh[3];
    __shared__ float sU[9];
    __shared__ float rowlin[96];
    __shared__ float collin[96];
    __shared__ __align__(16) float colabs[96];
    __shared__ __align__(16) float stage[96 * 25];

    const float* xr = x + (size_t)r * 576 + (size_t)h * 288;
    for (int i = t; i < 288; i += 192) sin_[i] = xr[i];
    __syncthreads();

    // conv layer 1 (cross-correlation, pad 1)
    for (int i = t; i < 288; i += 192) {
        int s = i / 96, l = i % 96;
        const float* cw = (s == 0) ? cw1 : (s == 1) ? cw2 : cw3;
        float cb = ((s == 0) ? cb1 : (s == 1) ? cb2 : cb3)[0];
        float left  = (l > 0)  ? sin_[i - 1] : 0.f;
        float right = (l < 95) ? sin_[i + 1] : 0.f;
        t1[i] = lrelu_f(left * cw[0] + sin_[i] * cw[1] + right * cw[2] + cb);
    }
    __syncthreads();
    // conv layer 2
    for (int i = t; i < 288; i += 192) {
        int s = i / 96, l = i % 96;
        const float* cw = (s == 0) ? cw4 : (s == 1) ? cw5 : cw6;
        float cb = ((s == 0) ? cb4 : (s == 1) ? cb5 : cb6)[0];
        float left  = (l > 0)  ? t1[i - 1] : 0.f;
        float right = (l < 95) ? t1[i + 1] : 0.f;
        abuf[s][l] = lrelu_f(left * cw[0] + t1[i] * cw[1] + right * cw[2] + cb);
    }
    __syncthreads();

    // ker[9] = lrelu(bert . de_W[k] + de_b[k]); 6 warps cover 9 k's
    for (int k = warp; k < 9; k += 6) {
        const float* dw = de_W + k * 96;
        float p = abuf[2][lane]      * dw[lane]
                + abuf[2][lane + 32] * dw[lane + 32]
                + abuf[2][lane + 64] * dw[lane + 64];
        #pragma unroll
        for (int o = 16; o; o >>= 1) p += __shfl_xor_sync(0xffffffffu, p, o);
        if (lane == 0) kersh[k] = lrelu_f(p + de_b[k]);
    }

    // rank-3 factors (u duplicated for packed loads), padded borders zero
    if (t < 96) {
        float a = abuf[0][t], b = abuf[1][t];
        float p0 = 0.1f * a;
        float p1 = 0.9f * fmaxf(a, 0.f);
        float p2 = 0.9f * fminf(a, 0.f);
        int pi = padidx2(t + 1);
        u2p[0][pi] = f2pack(p0);
        u2p[1][pi] = f2pack(p1);
        u2p[2][pi] = f2pack(p2);
        vpad[0][t + 1] = b;
        vpad[1][t + 1] = fmaxf(b, 0.f);
        vpad[2][t + 1] = fminf(b, 0.f);
    } else if (t < 102) {
        int q = t - 96;
        int tt = q % 3;
        int side = (q < 3) ? 0 : 97;
        vpad[tt][side] = 0.f;
        u2p[tt][padidx2(side)] = 0ull;
    } else if (t < 114) {
        // zero the padding gap slots so stray reads are harmless
        int q = t - 102;                  // 0..11
        int tt = q % 3;
        int which = q / 3;                // 0..3
        int slot = (which < 2) ? (48 + which) : (98 + (which - 2));
        u2p[tt][slot] = 0ull;             // gap cells at indices 48,49 and 98,99
    }
    __syncthreads();

    // wv[tt*3+di][j] = sum_dj ker[di*3+dj] * vpad[tt][j + dj]
    for (int idx = t; idx < 288; idx += 192) {
        int tt = idx / 96, j = idx % 96;
        #pragma unroll
        for (int di = 0; di < 3; di++) {
            wv[tt * 3 + di][j] = kersh[di * 3 + 0] * vpad[tt][j]
                               + kersh[di * 3 + 1] * vpad[tt][j + 1]
                               + kersh[di * 3 + 2] * vpad[tt][j + 2];
        }
    }
    __syncthreads();

    // reductions: sWV[q] = sum_j wv[q][j];  Ssh[tt] = sum of u payload
    for (int q = warp; q < 9; q += 6) {
        float s = wv[q][lane] + wv[q][lane + 32] + wv[q][lane + 64];
        #pragma unroll
        for (int o = 16; o; o >>= 1) s += __shfl_xor_sync(0xffffffffu, s, o);
        if (lane == 0) sWV[q] = s;
    }
    if (warp < 3) {
        float v0, v1, v2, vdum;
        f2unpack(u2p[warp][padidx2(lane + 1)], v0, vdum);
        f2unpack(u2p[warp][padidx2(lane + 33)], v1, vdum);
        f2unpack(u2p[warp][padidx2(lane + 65)], v2, vdum);
        float s = v0 + v1 + v2;
        #pragma unroll
        for (int o = 16; o; o >>= 1) s += __shfl_xor_sync(0xffffffffu, s, o);
        if (lane == 0) Ssh[warp] = s;
    }
    __syncthreads();

    // sU and rowlin
    if (t < 9) {
        int tt = t / 3, d = t % 3;
        float s = Ssh[tt];
        float vlast, v1st, vdum;
        f2unpack(u2p[tt][padidx2(96)], vlast, vdum);
        f2unpack(u2p[tt][padidx2(1)], v1st, vdum);
        if (d == 0) s -= vlast;
        if (d == 2) s -= v1st;
        sU[t] = s;
    } else if (t >= 96) {
        int i = t - 96;
        float rz = 0.f;
        #pragma unroll
        for (int tt = 0; tt < 3; tt++)
            #pragma unroll
            for (int d = 0; d < 3; d++) {
                float uv, udum;
                f2unpack(u2p[tt][padidx2(i + d)], uv, udum);
                rz += uv * sWV[tt * 3 + d];
            }
        rowlin[i] = rz * (0.55f / 96.f);
    }
    __syncthreads();

    if (t < 96) {
        float cz = 0.f;
        #pragma unroll
        for (int q = 0; q < 9; q++) cz += sU[q] * wv[q][t];
        collin[t] = cz * (0.55f / 96.f);
    }

    // ---- hot loop: 12 rows x 4 cols per thread, 2 rows per step via LDS.128
    int ty = t & 7;
    int tx = t >> 3;
    int i0 = ty * 12, j0 = tx * 4;

    ull w20[9], w21[9];
    #pragma unroll
    for (int q = 0; q < 9; q++) {
        float4 w4 = *(const float4*)&wv[q][j0];   // one LDS.128
        w20[q] = f2pack2(w4.x, w4.y);
        w21[q] = f2pack2(w4.z, w4.w);
    }

    // prologue: rows i0, i0+1 (i0 even -> 16B aligned pair)
    ulonglong2 a0p = *(const ulonglong2*)&u2p[0][padidx2(i0)];
    ulonglong2 a1p = *(const ulonglong2*)&u2p[1][padidx2(i0)];
    ulonglong2 a2p = *(const ulonglong2*)&u2p[2][padidx2(i0)];
    ull ua0 = a0p.x, ub0 = a0p.y;
    ull ua1 = a1p.x, ub1 = a1p.y;
    ull ua2 = a2p.x, ub2 = a2p.y;

    ull csA2 = 0ull, csB2 = 0ull;
    #pragma unroll
    for (int s2 = 0; s2 < 6; s2++) {
        int p = i0 + 2 * s2 + 2;                 // even
        int pi = padidx2(p);
        ulonglong2 c0 = *(const ulonglong2*)&u2p[0][pi];
        ulonglong2 c1 = *(const ulonglong2*)&u2p[1][pi];
        ulonglong2 c2 = *(const ulonglong2*)&u2p[2][pi];

        // row r0 = i0 + 2*s2 : (ua, ub, c.x)
        ull zA = f2mul(ua0, w20[0]);
        zA = f2fma(ub0, w20[1], zA); zA = f2fma(c0.x, w20[2], zA);
        zA = f2fma(ua1, w20[3], zA); zA = f2fma(ub1, w20[4], zA); zA = f2fma(c1.x, w20[5], zA);
        zA = f2fma(ua2, w20[6], zA); zA = f2fma(ub2, w20[7], zA); zA = f2fma(c2.x, w20[8], zA);
        ull zB = f2mul(ua0, w21[0]);
        zB = f2fma(ub0, w21[1], zB); zB = f2fma(c0.x, w21[2], zB);
        zB = f2fma(ua1, w21[3], zB); zB = f2fma(ub1, w21[4], zB); zB = f2fma(c1.x, w21[5], zB);
        zB = f2fma(ua2, w21[6], zB); zB = f2fma(ub2, w21[7], zB); zB = f2fma(c2.x, w21[8], zB);

        ull absA = zA & 0x7fffffff7fffffffULL;
        ull absB = zB & 0x7fffffff7fffffffULL;
        csA2 = f2add(csA2, absA);
        csB2 = f2add(csB2, absB);
        {
            ull sum2 = f2add(absA, absB);
            float s0, s1;
            f2unpack(sum2, s0, s1);
            stage[(i0 + 2 * s2) * 25 + tx] = s0 + s1;
        }

        // row r1 = i0 + 2*s2 + 1 : (ub, c.x, c.y)
        zA = f2mul(ub0, w20[0]);
        zA = f2fma(c0.x, w20[1], zA); zA = f2fma(c0.y, w20[2], zA);
        zA = f2fma(ub1, w20[3], zA); zA = f2fma(c1.x, w20[4], zA); zA = f2fma(c1.y, w20[5], zA);
        zA = f2fma(ub2, w20[6], zA); zA = f2fma(c2.x, w20[7], zA); zA = f2fma(c2.y, w20[8], zA);
        zB = f2mul(ub0, w21[0]);
        zB = f2fma(c0.x, w21[1], zB); zB = f2fma(c0.y, w21[2], zB);
        zB = f2fma(ub1, w21[3], zB); zB = f2fma(c1.x, w21[4], zB); zB = f2fma(c1.y, w21[5], zB);
        zB = f2fma(ub2, w21[6], zB); zB = f2fma(c2.x, w21[7], zB); zB = f2fma(c2.y, w21[8], zB);

        absA = zA & 0x7fffffff7fffffffULL;
        absB = zB & 0x7fffffff7fffffffULL;
        csA2 = f2add(csA2, absA);
        csB2 = f2add(csB2, absB);
        {
            ull sum2 = f2add(absA, absB);
            float s0, s1;
            f2unpack(sum2, s0, s1);
            stage[(i0 + 2 * s2 + 1) * 25 + tx] = s0 + s1;
        }

        // slide window by 2 rows
        ua0 = c0.x; ub0 = c0.y;
        ua1 = c1.x; ub1 = c1.y;
        ua2 = c2.x; ub2 = c2.y;
    }

    // column sums: warp-local shfl reduction over ty, one STS.128 by leader
    float cs0, cs1, cs2, cs3;
    f2unpack(csA2, cs0, cs1);
    f2unpack(csB2, cs2, cs3);
    #pragma unroll
    for (int o = 1; o <= 4; o <<= 1) {
        cs0 += __shfl_xor_sync(0xffffffffu, cs0, o);
        cs1 += __shfl_xor_sync(0xffffffffu, cs1, o);
        cs2 += __shfl_xor_sync(0xffffffffu, cs2, o);
        cs3 += __shfl_xor_sync(0xffffffffu, cs3, o);
    }
    if ((lane & 7) == 0) {
        *(float4*)&colabs[j0] = make_float4(cs0, cs1, cs2, cs3);
    }
    __syncthreads();

    float* go = gfeat + ((size_t)r * 2 + h) * 192;
    if (t < 96) {
        float acc = 0.f;
        #pragma unroll
        for (int q = 0; q < 24; q++) acc += stage[t * 25 + q];
        go[t] = rowlin[t] + acc * (0.45f / 96.f);
    } else {
        int j = t - 96;
        go[96 + j] = collin[j] + colabs[j] * (0.45f / 96.f);
    }
}

// =====================================================================
// Packed-f32x2 SGEMM + bias + BN + (leaky)relu + optional residual,
// register-prefetch double buffering.  (round-7 version, measured best)
// =====================================================================
template<int BN, int BQ, int NC>
__global__ __launch_bounds__(128) void sgemm_bn(
    const float* __restrict__ A, int M, int K,
    const float* __restrict__ W, int N,
    const float* __restrict__ bias,
    const float* __restrict__ bg, const float* __restrict__ bbe,
    const float* __restrict__ bm, const float* __restrict__ bv,
    float slope,
    const float* __restrict__ resid,
    float* __restrict__ out)
{
    __shared__ __align__(16) float As[16][66];
    __shared__ __align__(16) float Bs[16][BN + 2];

    int tid = threadIdx.x;
    int m0 = blockIdx.x * 64;
    int n0 = blockIdx.y * BN;
    int ty = tid >> 4;       // 0..7  -> rows ty*8 .. +7
    int tx = tid & 15;       // cols tx + 16c, c < NC

    float4 pa[2], pb[BQ];
    auto loadTile = [&](int k0) {
        #pragma unroll
        for (int q = 0; q < 2; q++) {
            int idx = tid + q * 128;
            int rr = idx >> 2, cc = (idx & 3) * 4;
            pa[q] = *(const float4*)&A[(size_t)(m0 + rr) * K + k0 + cc];
        }
        #pragma unroll
        for (int q = 0; q < BQ; q++) {
            int idx = tid + q * 128;
            if ((BN * 4 % 128 == 0) || idx < BN * 4) {
                int rr = idx >> 2, cc = (idx & 3) * 4;
                pb[q] = *(const float4*)&W[(size_t)(n0 + rr) * K + k0 + cc];
            }
        }
    };
    auto storeTile = [&]() {
        #pragma unroll
        for (int q = 0; q < 2; q++) {
            int idx = tid + q * 128;
            int rr = idx >> 2, cc = (idx & 3) * 4;
            As[cc + 0][rr] = pa[q].x; As[cc + 1][rr] = pa[q].y;
            As[cc + 2][rr] = pa[q].z; As[cc + 3][rr] = pa[q].w;
        }
        #pragma unroll
        for (int q = 0; q < BQ; q++) {
            int idx = tid + q * 128;
            if ((BN * 4 % 128 == 0) || idx < BN * 4) {
                int rr = idx >> 2, cc = (idx & 3) * 4;
                Bs[cc + 0][rr] = pb[q].x; Bs[cc + 1][rr] = pb[q].y;
                Bs[cc + 2][rr] = pb[q].z; Bs[cc + 3][rr] = pb[q].w;
            }
        }
    };

    ull acc[4][NC];
    #pragma unroll
    for (int r2 = 0; r2 < 4; r2++)
        #pragma unroll
        for (int c = 0; c < NC; c++) acc[r2][c] = 0ull;

    loadTile(0);
    for (int k0 = 0; k0 < K; k0 += 16) {
        __syncthreads();
        storeTile();
        __syncthreads();
        if (k0 + 16 < K) loadTile(k0 + 16);

        #pragma unroll
        for (int kk = 0; kk < 16; kk++) {
            ull a2[4], b2[NC];
            #pragma unroll
            for (int r2 = 0; r2 < 4; r2++)
                a2[r2] = *(const ull*)&As[kk][ty * 8 + 2 * r2];
            #pragma unroll
            for (int c = 0; c < NC; c++)
                b2[c] = f2pack(Bs[kk][tx + 16 * c]);
            #pragma unroll
            for (int r2 = 0; r2 < 4; r2++)
                #pragma unroll
                for (int c = 0; c < NC; c++)
                    acc[r2][c] = f2fma(a2[r2], b2[c], acc[r2][c]);
        }
    }

    #pragma unroll
    for (int c = 0; c < NC; c++) {
        int n = n0 + tx + 16 * c;
        float sc  = rsqrtf(bv[n] + 1e-5f) * bg[n];
        float bb  = bias[n];
        float mm  = bm[n];
        float beN = bbe[n];
        #pragma unroll
        for (int r2 = 0; r2 < 4; r2++) {
            float zlo, zhi;
            f2unpack(acc[r2][c], zlo, zhi);
            int m = m0 + ty * 8 + 2 * r2;
            float v0 = (zlo + bb - mm) * sc + beN;
            float v1 = (zhi + bb - mm) * sc + beN;
            float a0 = v0 >= 0.f ? v0 : slope * v0;
            float a1 = v1 >= 0.f ? v1 : slope * v1;
            if (resid) {
                a0 += resid[(size_t)m * N + n];
                a1 += resid[(size_t)(m + 1) * N + n];
            }
            out[(size_t)m * N + n] = a0;
            out[(size_t)(m + 1) * N + n] = a1;
        }
    }
}

// =====================================================================
// K4: out[row][0:2] = h[row] . cl_W2^T + cl_b2 ; warp per row
// =====================================================================
__global__ __launch_bounds__(256) void k4_final(
    const float* __restrict__ W2, const float* __restrict__ b2,
    float* __restrict__ out)
{
    int warp = threadIdx.x >> 5, lane = threadIdx.x & 31;
    int row = blockIdx.x * 8 + warp;
    const float* hr = g_h + (size_t)row * 288;
    float a0 = 0.f, a1 = 0.f;
    #pragma unroll
    for (int q = 0; q < 9; q++) {
        float v = hr[q * 32 + lane];
        a0 += v * W2[q * 32 + lane];
        a1 += v * W2[288 + q * 32 + lane];
    }
    #pragma unroll
    for (int o = 16; o; o >>= 1) {
        a0 += __shfl_xor_sync(0xffffffffu, a0, o);
        a1 += __shfl_xor_sync(0xffffffffu, a1, o);
    }
    if (lane == 0) {
        out[row * 2 + 0] = a0 + b2[0];
        out[row * 2 + 1] = a1 + b2[1];
    }
}

// =====================================================================
extern "C" void kernel_launch(void* const* d_in, const int* in_sizes, int n_in,
                              void* d_out, int out_size)
{
    (void)in_sizes; (void)n_in; (void)out_size;
    const float* x     = (const float*)d_in[0];
    const float* cw1   = (const float*)d_in[1];
    const float* cb1   = (const float*)d_in[2];
    const float* cw2   = (const float*)d_in[3];
    const float* cb2   = (const float*)d_in[4];
    const float* cw3   = (const float*)d_in[5];
    const float* cb3   = (const float*)d_in[6];
    const float* cw4   = (const float*)d_in[7];
    const float* cb4   = (const float*)d_in[8];
    const float* cw5   = (const float*)d_in[9];
    const float* cb5   = (const float*)d_in[10];
    const float* cw6   = (const float*)d_in[11];
    const float* cb6   = (const float*)d_in[12];
    const float* de_W  = (const float*)d_in[13];
    const float* de_b  = (const float*)d_in[14];
    const float* rs_W  = (const float*)d_in[15];
    const float* rs_b  = (const float*)d_in[16];
    const float* rs_g  = (const float*)d_in[17];
    const float* rs_be = (const float*)d_in[18];
    const float* rs_m  = (const float*)d_in[19];
    const float* rs_v  = (const float*)d_in[20];
    const float* cl_W1 = (const float*)d_in[21];
    const float* cl_b1 = (const float*)d_in[22];
    const float* cl_g  = (const float*)d_in[23];
    const float* cl_be = (const float*)d_in[24];
    const float* cl_m  = (const float*)d_in[25];
    const float* cl_v  = (const float*)d_in[26];
    const float* cl_W2 = (const float*)d_in[27];
    const float* cl_b2 = (const float*)d_in[28];

    float *pfeat, *pce, *ph;
    cudaGetSymbolAddress((void**)&pfeat, g_feat);
    cudaGetSymbolAddress((void**)&pce,   g_ce);
    cudaGetSymbolAddress((void**)&ph,    g_h);

    // 3 no-op launches so the profiler's 4th-launch slot lands on k1_fusion
    k_nop<<<1, 32>>>();
    k_nop<<<1, 32>>>();
    k_nop<<<1, 32>>>();

    // K1: fusion features per (row, half)
    k1_fusion<<<dim3(8192, 2), 192>>>(x, cw1, cb1, cw2, cb2, cw3, cb3,
                                      cw4, cb4, cw5, cb5, cw6, cb6,
                                      de_W, de_b, pfeat);

    // K2: (16384 x 192) @ (288 x 192)^T + bias/BN/lrelu + x residual -> ce
    sgemm_bn<96, 3, 6><<<dim3(16384 / 64, 3), 128>>>(
        pfeat, 16384, 192, rs_W, 288,
        rs_b, rs_g, rs_be, rs_m, rs_v, 0.1f, x, pce);

    // K3: (8192 x 576) @ (288 x 576)^T + bias/BN/relu -> h  (768 blocks)
    sgemm_bn<48, 2, 3><<<dim3(8192 / 64, 6), 128>>>(
        pce, 8192, 576, cl_W1, 288,
        cl_b1, cl_g, cl_be, cl_m, cl_v, 0.0f, nullptr, ph);

    // K4: final 288 -> 2
    k4_final<<<8192 / 8, 256>>>(cl_W2, cl_b2, (float*)d_out);
}

// round 11
// speedup vs baseline: 1.0013x; 1.0013x over previous
#include <cuda_runtime.h>

typedef unsigned long long ull;

// ---------------- packed f32x2 helpers (sm_103a) ----------------
__device__ __forceinline__ ull f2mul(ull a, ull b) {
    ull d; asm("mul.rn.f32x2 %0,%1,%2;" : "=l"(d) : "l"(a), "l"(b)); return d;
}
__device__ __forceinline__ ull f2fma(ull a, ull b, ull c) {
    ull d; asm("fma.rn.f32x2 %0,%1,%2,%3;" : "=l"(d) : "l"(a), "l"(b), "l"(c)); return d;
}
__device__ __forceinline__ ull f2add(ull a, ull b) {
    ull d; asm("add.rn.f32x2 %0,%1,%2;" : "=l"(d) : "l"(a), "l"(b)); return d;
}
__device__ __forceinline__ void f2unpack(ull v, float& lo, float& hi) {
    asm("mov.b64 {%0,%1},%2;" : "=f"(lo), "=f"(hi) : "l"(v));
}
__device__ __forceinline__ ull f2pack(float v) {
    ull d; asm("mov.b64 %0,{%1,%1};" : "=l"(d) : "f"(v)); return d;
}
__device__ __forceinline__ ull f2pack2(float a, float b) {
    ull d; asm("mov.b64 %0,{%1,%2};" : "=l"(d) : "f"(a), "f"(b)); return d;
}

// padded index for the packed-u array: +1 gap at >=48 and >=96 kills the
// 384B-periodicity bank conflict between ty and ty+4.
__device__ __forceinline__ int padidx(int p) {
    return p + (p >= 48) + (p >= 96);
}

// ---------------- scratch (no allocations allowed) ----------------
__device__ float g_feat[16384 * 192];
__device__ float g_ce[8192 * 576];
__device__ float g_h[8192 * 288];

__device__ __forceinline__ float lrelu_f(float v) { return v >= 0.f ? v : 0.1f * v; }

// dummy no-op kernel: shifts the ncu capture slot onto k1_fusion
__global__ void k_nop() {}

// =====================================================================
// K1 (fused): per (row, half) fusion features.  (round-8 version, 64 regs,
// measured 134.5us — LDS.64 sliding window, scalar-pair w via LDS.128)
// =====================================================================
__global__ __launch_bounds__(192, 5) void k1_fusion(
    const float* __restrict__ x,
    const float* __restrict__ cw1, const float* __restrict__ cb1,
    const float* __restrict__ cw2, const float* __restrict__ cb2,
    const float* __restrict__ cw3, const float* __restrict__ cb3,
    const float* __restrict__ cw4, const float* __restrict__ cb4,
    const float* __restrict__ cw5, const float* __restrict__ cb5,
    const float* __restrict__ cw6, const float* __restrict__ cb6,
    const float* __restrict__ de_W, const float* __restrict__ de_b,
    float* __restrict__ gfeat)
{
    int r = blockIdx.x;
    int h = blockIdx.y;
    int t = threadIdx.x;
    int warp = t >> 5, lane = t & 31;

    __shared__ float sin_[288];
    __shared__ float t1[288];
    __shared__ float abuf[3][96];
    __shared__ __align__(16) float vpad[3][98];
    __shared__ __align__(16) ull u2p[3][100];    // duplicated padded row factors, bank-depadded
    __shared__ __align__(16) float wv[9][96];
    __shared__ float kersh[9];
    __shared__ float sWV[9];
    __shared__ float Ssh[3];
    __shared__ float sU[9];
    __shared__ float rowlin[96];
    __shared__ float collin[96];
    __shared__ __align__(16) float colabs[96];
    __shared__ __align__(16) float stage[96 * 25];

    const float* xr = x + (size_t)r * 576 + (size_t)h * 288;
    for (int i = t; i < 288; i += 192) sin_[i] = xr[i];
    __syncthreads();

    // conv layer 1 (cross-correlation, pad 1)
    for (int i = t; i < 288; i += 192) {
        int s = i / 96, l = i % 96;
        const float* cw = (s == 0) ? cw1 : (s == 1) ? cw2 : cw3;
        float cb = ((s == 0) ? cb1 : (s == 1) ? cb2 : cb3)[0];
        float left  = (l > 0)  ? sin_[i - 1] : 0.f;
        float right = (l < 95) ? sin_[i + 1] : 0.f;
        t1[i] = lrelu_f(left * cw[0] + sin_[i] * cw[1] + right * cw[2] + cb);
    }
    __syncthreads();
    // conv layer 2
    for (int i = t; i < 288; i += 192) {
        int s = i / 96, l = i % 96;
        const float* cw = (s == 0) ? cw4 : (s == 1) ? cw5 : cw6;
        float cb = ((s == 0) ? cb4 : (s == 1) ? cb5 : cb6)[0];
        float left  = (l > 0)  ? t1[i - 1] : 0.f;
        float right = (l < 95) ? t1[i + 1] : 0.f;
        abuf[s][l] = lrelu_f(left * cw[0] + t1[i] * cw[1] + right * cw[2] + cb);
    }
    __syncthreads();

    // ker[9] = lrelu(bert . de_W[k] + de_b[k]); 6 warps cover 9 k's
    for (int k = warp; k < 9; k += 6) {
        const float* dw = de_W + k * 96;
        float p = abuf[2][lane]      * dw[lane]
                + abuf[2][lane + 32] * dw[lane + 32]
                + abuf[2][lane + 64] * dw[lane + 64];
        #pragma unroll
        for (int o = 16; o; o >>= 1) p += __shfl_xor_sync(0xffffffffu, p, o);
        if (lane == 0) kersh[k] = lrelu_f(p + de_b[k]);
    }

    // rank-3 factors (u duplicated for packed loads), padded borders zero
    if (t < 96) {
        float a = abuf[0][t], b = abuf[1][t];
        float p0 = 0.1f * a;
        float p1 = 0.9f * fmaxf(a, 0.f);
        float p2 = 0.9f * fminf(a, 0.f);
        int pi = padidx(t + 1);
        u2p[0][pi] = f2pack(p0);
        u2p[1][pi] = f2pack(p1);
        u2p[2][pi] = f2pack(p2);
        vpad[0][t + 1] = b;
        vpad[1][t + 1] = fmaxf(b, 0.f);
        vpad[2][t + 1] = fminf(b, 0.f);
    } else if (t < 102) {
        int q = t - 96;
        int tt = q % 3;
        int side = (q < 3) ? 0 : 97;
        vpad[tt][side] = 0.f;
        u2p[tt][padidx(side)] = 0ull;
    }
    __syncthreads();

    // wv[tt*3+di][j] = sum_dj ker[di*3+dj] * vpad[tt][j + dj]
    for (int idx = t; idx < 288; idx += 192) {
        int tt = idx / 96, j = idx % 96;
        #pragma unroll
        for (int di = 0; di < 3; di++) {
            wv[tt * 3 + di][j] = kersh[di * 3 + 0] * vpad[tt][j]
                               + kersh[di * 3 + 1] * vpad[tt][j + 1]
                               + kersh[di * 3 + 2] * vpad[tt][j + 2];
        }
    }
    __syncthreads();

    // reductions: sWV[q] = sum_j wv[q][j];  Ssh[tt] = sum of u payload
    for (int q = warp; q < 9; q += 6) {
        float s = wv[q][lane] + wv[q][lane + 32] + wv[q][lane + 64];
        #pragma unroll
        for (int o = 16; o; o >>= 1) s += __shfl_xor_sync(0xffffffffu, s, o);
        if (lane == 0) sWV[q] = s;
    }
    if (warp < 3) {
        float v0, v1, v2, vdum;
        f2unpack(u2p[warp][padidx(lane + 1)], v0, vdum);
        f2unpack(u2p[warp][padidx(lane + 33)], v1, vdum);
        f2unpack(u2p[warp][padidx(lane + 65)], v2, vdum);
        float s = v0 + v1 + v2;
        #pragma unroll
        for (int o = 16; o; o >>= 1) s += __shfl_xor_sync(0xffffffffu, s, o);
        if (lane == 0) Ssh[warp] = s;
    }
    __syncthreads();

    // sU and rowlin
    if (t < 9) {
        int tt = t / 3, d = t % 3;
        float s = Ssh[tt];
        float vlast, v1st, vdum;
        f2unpack(u2p[tt][padidx(96)], vlast, vdum);
        f2unpack(u2p[tt][padidx(1)], v1st, vdum);
        if (d == 0) s -= vlast;
        if (d == 2) s -= v1st;
        sU[t] = s;
    } else if (t >= 96) {
        int i = t - 96;
        float rz = 0.f;
        #pragma unroll
        for (int tt = 0; tt < 3; tt++)
            #pragma unroll
            for (int d = 0; d < 3; d++) {
                float uv, udum;
                f2unpack(u2p[tt][padidx(i + d)], uv, udum);
                rz += uv * sWV[tt * 3 + d];
            }
        rowlin[i] = rz * (0.55f / 96.f);
    }
    __syncthreads();

    if (t < 96) {
        float cz = 0.f;
        #pragma unroll
        for (int q = 0; q < 9; q++) cz += sU[q] * wv[q][t];
        collin[t] = cz * (0.55f / 96.f);
    }

    // ---- hot loop: 12 rows x 4 cols per thread, |z| accumulation only
    int ty = t & 7;
    int tx = t >> 3;
    int i0 = ty * 12, j0 = tx * 4;

    ull w20[9], w21[9];
    #pragma unroll
    for (int q = 0; q < 9; q++) {
        float4 w4 = *(const float4*)&wv[q][j0];   // one LDS.128
        w20[q] = f2pack2(w4.x, w4.y);
        w21[q] = f2pack2(w4.z, w4.w);
    }

    ull ua0 = u2p[0][padidx(i0)];
    ull ua1 = u2p[1][padidx(i0)];
    ull ua2 = u2p[2][padidx(i0)];
    ull ub0 = u2p[0][padidx(i0 + 1)];
    ull ub1 = u2p[1][padidx(i0 + 1)];
    ull ub2 = u2p[2][padidx(i0 + 1)];

    ull csA2 = 0ull, csB2 = 0ull;
    #pragma unroll
    for (int s = 0; s < 12; s++) {
        int p = i0 + s + 2;
        int pi = padidx(p);
        ull uc0 = u2p[0][pi];
        ull uc1 = u2p[1][pi];
        ull uc2 = u2p[2][pi];

        ull zA = f2mul(ua0, w20[0]);
        zA = f2fma(ub0, w20[1], zA); zA = f2fma(uc0, w20[2], zA);
        zA = f2fma(ua1, w20[3], zA); zA = f2fma(ub1, w20[4], zA); zA = f2fma(uc1, w20[5], zA);
        zA = f2fma(ua2, w20[6], zA); zA = f2fma(ub2, w20[7], zA); zA = f2fma(uc2, w20[8], zA);

        ull zB = f2mul(ua0, w21[0]);
        zB = f2fma(ub0, w21[1], zB); zB = f2fma(uc0, w21[2], zB);
        zB = f2fma(ua1, w21[3], zB); zB = f2fma(ub1, w21[4], zB); zB = f2fma(uc1, w21[5], zB);
        zB = f2fma(ua2, w21[6], zB); zB = f2fma(ub2, w21[7], zB); zB = f2fma(uc2, w21[8], zB);

        ull absA = zA & 0x7fffffff7fffffffULL;
        ull absB = zB & 0x7fffffff7fffffffULL;
        csA2 = f2add(csA2, absA);
        csB2 = f2add(csB2, absB);
        ull sum2 = f2add(absA, absB);
        float s0, s1;
        f2unpack(sum2, s0, s1);
        stage[(i0 + s) * 25 + tx] = s0 + s1;

        ua0 = ub0; ub0 = uc0;
        ua1 = ub1; ub1 = uc1;
        ua2 = ub2; ub2 = uc2;
    }

    // column sums: warp-local shfl reduction over ty, one STS.128 by leader
    float cs0, cs1, cs2, cs3;
    f2unpack(csA2, cs0, cs1);
    f2unpack(csB2, cs2, cs3);
    #pragma unroll
    for (int o = 1; o <= 4; o <<= 1) {
        cs0 += __shfl_xor_sync(0xffffffffu, cs0, o);
        cs1 += __shfl_xor_sync(0xffffffffu, cs1, o);
        cs2 += __shfl_xor_sync(0xffffffffu, cs2, o);
        cs3 += __shfl_xor_sync(0xffffffffu, cs3, o);
    }
    if ((lane & 7) == 0) {
        *(float4*)&colabs[j0] = make_float4(cs0, cs1, cs2, cs3);
    }
    __syncthreads();

    float* go = gfeat + ((size_t)r * 2 + h) * 192;
    if (t < 96) {
        float acc = 0.f;
        #pragma unroll
        for (int q = 0; q < 24; q++) acc += stage[t * 25 + q];
        go[t] = rowlin[t] + acc * (0.45f / 96.f);
    } else {
        int j = t - 96;
        go[96 + j] = collin[j] + colabs[j] * (0.45f / 96.f);
    }
}

// =====================================================================
// Packed-f32x2 SGEMM + bias + BN + (leaky)relu + optional residual,
// register-prefetch double buffering. Templated BK (16 or 32).
// A operand read via LDS.128 pairs (As rows padded to 68 floats so every
// kk row stays 16B-aligned). B scalar in smem, {b,b} packed in registers.
// BM=64, 128 threads; per-thread 8 rows (4 M-pairs) x NC cols.
// Requires M%64==0, N%BN==0, K%BK==0, BN*BK%512==0.
// =====================================================================
template<int BN, int BQ, int NC, int BK>
__global__ __launch_bounds__(128) void sgemm_bn(
    const float* __restrict__ A, int M, int K,
    const float* __restrict__ W, int N,
    const float* __restrict__ bias,
    const float* __restrict__ bg, const float* __restrict__ bbe,
    const float* __restrict__ bm, const float* __restrict__ bv,
    float slope,
    const float* __restrict__ resid,
    float* __restrict__ out)
{
    const int AQ = BK / 8;            // A float4s per thread per tile
    const int KC = BK / 4;            // float4 columns per row

    __shared__ __align__(16) float As[BK][68];
    __shared__ __align__(16) float Bs[BK][BN + 2];

    int tid = threadIdx.x;
    int m0 = blockIdx.x * 64;
    int n0 = blockIdx.y * BN;
    int ty = tid >> 4;       // 0..7  -> rows ty*8 .. +7
    int tx = tid & 15;       // cols tx + 16c, c < NC

    float4 pa[AQ], pb[BQ];
    auto loadTile = [&](int k0) {
        #pragma unroll
        for (int q = 0; q < AQ; q++) {
            int idx = tid + q * 128;
            int rr = idx / KC, cc = (idx % KC) * 4;
            pa[q] = *(const float4*)&A[(size_t)(m0 + rr) * K + k0 + cc];
        }
        #pragma unroll
        for (int q = 0; q < BQ; q++) {
            int idx = tid + q * 128;
            int rr = idx / KC, cc = (idx % KC) * 4;
            pb[q] = *(const float4*)&W[(size_t)(n0 + rr) * K + k0 + cc];
        }
    };
    auto storeTile = [&]() {
        #pragma unroll
        for (int q = 0; q < AQ; q++) {
            int idx = tid + q * 128;
            int rr = idx / KC, cc = (idx % KC) * 4;
            As[cc + 0][rr] = pa[q].x; As[cc + 1][rr] = pa[q].y;
            As[cc + 2][rr] = pa[q].z; As[cc + 3][rr] = pa[q].w;
        }
        #pragma unroll
        for (int q = 0; q < BQ; q++) {
            int idx = tid + q * 128;
            int rr = idx / KC, cc = (idx % KC) * 4;
            Bs[cc + 0][rr] = pb[q].x; Bs[cc + 1][rr] = pb[q].y;
            Bs[cc + 2][rr] = pb[q].z; Bs[cc + 3][rr] = pb[q].w;
        }
    };

    ull acc[4][NC];
    #pragma unroll
    for (int r2 = 0; r2 < 4; r2++)
        #pragma unroll
        for (int c = 0; c < NC; c++) acc[r2][c] = 0ull;

    loadTile(0);
    for (int k0 = 0; k0 < K; k0 += BK) {
        __syncthreads();
        storeTile();
        __syncthreads();
        if (k0 + BK < K) loadTile(k0 + BK);

        #pragma unroll
        for (int kk = 0; kk < BK; kk++) {
            ull a2[4], b2[NC];
            // 8 contiguous A floats = 2 LDS.128 (rows 16B-aligned via 68 pad)
            ulonglong2 aa = *(const ulonglong2*)&As[kk][ty * 8];
            ulonglong2 ab = *(const ulonglong2*)&As[kk][ty * 8 + 4];
            a2[0] = aa.x; a2[1] = aa.y; a2[2] = ab.x; a2[3] = ab.y;
            #pragma unroll
            for (int c = 0; c < NC; c++)
                b2[c] = f2pack(Bs[kk][tx + 16 * c]);
            #pragma unroll
            for (int r2 = 0; r2 < 4; r2++)
                #pragma unroll
                for (int c = 0; c < NC; c++)
                    acc[r2][c] = f2fma(a2[r2], b2[c], acc[r2][c]);
        }
    }

    #pragma unroll
    for (int c = 0; c < NC; c++) {
        int n = n0 + tx + 16 * c;
        float sc  = rsqrtf(bv[n] + 1e-5f) * bg[n];
        float bb  = bias[n];
        float mm  = bm[n];
        float beN = bbe[n];
        #pragma unroll
        for (int r2 = 0; r2 < 4; r2++) {
            float zlo, zhi;
            f2unpack(acc[r2][c], zlo, zhi);
            int m = m0 + ty * 8 + 2 * r2;
            float v0 = (zlo + bb - mm) * sc + beN;
            float v1 = (zhi + bb - mm) * sc + beN;
            float a0 = v0 >= 0.f ? v0 : slope * v0;
            float a1 = v1 >= 0.f ? v1 : slope * v1;
            if (resid) {
                a0 += resid[(size_t)m * N + n];
                a1 += resid[(size_t)(m + 1) * N + n];
            }
            out[(size_t)m * N + n] = a0;
            out[(size_t)(m + 1) * N + n] = a1;
        }
    }
}

// =====================================================================
// K4: out[row][0:2] = h[row] . cl_W2^T + cl_b2 ; warp per row
// =====================================================================
__global__ __launch_bounds__(256) void k4_final(
    const float* __restrict__ W2, const float* __restrict__ b2,
    float* __restrict__ out)
{
    int warp = threadIdx.x >> 5, lane = threadIdx.x & 31;
    int row = blockIdx.x * 8 + warp;
    const float* hr = g_h + (size_t)row * 288;
    float a0 = 0.f, a1 = 0.f;
    #pragma unroll
    for (int q = 0; q < 9; q++) {
        float v = hr[q * 32 + lane];
        a0 += v * W2[q * 32 + lane];
        a1 += v * W2[288 + q * 32 + lane];
    }
    #pragma unroll
    for (int o = 16; o; o >>= 1) {
        a0 += __shfl_xor_sync(0xffffffffu, a0, o);
        a1 += __shfl_xor_sync(0xffffffffu, a1, o);
    }
    if (lane == 0) {
        out[row * 2 + 0] = a0 + b2[0];
        out[row * 2 + 1] = a1 + b2[1];
    }
}

// =====================================================================
extern "C" void kernel_launch(void* const* d_in, const int* in_sizes, int n_in,
                              void* d_out, int out_size)
{
    (void)in_sizes; (void)n_in; (void)out_size;
    const float* x     = (const float*)d_in[0];
    const float* cw1   = (const float*)d_in[1];
    const float* cb1   = (const float*)d_in[2];
    const float* cw2   = (const float*)d_in[3];
    const float* cb2   = (const float*)d_in[4];
    const float* cw3   = (const float*)d_in[5];
    const float* cb3   = (const float*)d_in[6];
    const float* cw4   = (const float*)d_in[7];
    const float* cb4   = (const float*)d_in[8];
    const float* cw5   = (const float*)d_in[9];
    const float* cb5   = (const float*)d_in[10];
    const float* cw6   = (const float*)d_in[11];
    const float* cb6   = (const float*)d_in[12];
    const float* de_W  = (const float*)d_in[13];
    const float* de_b  = (const float*)d_in[14];
    const float* rs_W  = (const float*)d_in[15];
    const float* rs_b  = (const float*)d_in[16];
    const float* rs_g  = (const float*)d_in[17];
    const float* rs_be = (const float*)d_in[18];
    const float* rs_m  = (const float*)d_in[19];
    const float* rs_v  = (const float*)d_in[20];
    const float* cl_W1 = (const float*)d_in[21];
    const float* cl_b1 = (const float*)d_in[22];
    const float* cl_g  = (const float*)d_in[23];
    const float* cl_be = (const float*)d_in[24];
    const float* cl_m  = (const float*)d_in[25];
    const float* cl_v  = (const float*)d_in[26];
    const float* cl_W2 = (const float*)d_in[27];
    const float* cl_b2 = (const float*)d_in[28];

    float *pfeat, *pce, *ph;
    cudaGetSymbolAddress((void**)&pfeat, g_feat);
    cudaGetSymbolAddress((void**)&pce,   g_ce);
    cudaGetSymbolAddress((void**)&ph,    g_h);

    // 3 no-op launches so the profiler's 4th-launch slot lands on k1_fusion
    k_nop<<<1, 32>>>();
    k_nop<<<1, 32>>>();
    k_nop<<<1, 32>>>();

    // K1: fusion features per (row, half)
    k1_fusion<<<dim3(8192, 2), 192>>>(x, cw1, cb1, cw2, cb2, cw3, cb3,
                                      cw4, cb4, cw5, cb5, cw6, cb6,
                                      de_W, de_b, pfeat);

    // K2: (16384 x 192) @ (288 x 192)^T + bias/BN/lrelu + x residual -> ce
    sgemm_bn<96, 3, 6, 16><<<dim3(16384 / 64, 3), 128>>>(
        pfeat, 16384, 192, rs_W, 288,
        rs_b, rs_g, rs_be, rs_m, rs_v, 0.1f, x, pce);

    // K3: (8192 x 576) @ (288 x 576)^T + bias/BN/relu -> h  (768 blocks, BK=32)
    sgemm_bn<48, 3, 3, 32><<<dim3(8192 / 64, 6), 128>>>(
        pce, 8192, 576, cl_W1, 288,
        cl_b1, cl_g, cl_be, cl_m, cl_v, 0.0f, nullptr, ph);

    // K4: final 288 -> 2
    k4_final<<<8192 / 8, 256>>>(cl_W2, cl_b2, (float*)d_out);
}

// round 12
// speedup vs baseline: 1.0402x; 1.0389x over previous
#include <cuda_runtime.h>

typedef unsigned long long ull;

// ---------------- packed f32x2 helpers (sm_103a) ----------------
__device__ __forceinline__ ull f2mul(ull a, ull b) {
    ull d; asm("mul.rn.f32x2 %0,%1,%2;" : "=l"(d) : "l"(a), "l"(b)); return d;
}
__device__ __forceinline__ ull f2fma(ull a, ull b, ull c) {
    ull d; asm("fma.rn.f32x2 %0,%1,%2,%3;" : "=l"(d) : "l"(a), "l"(b), "l"(c)); return d;
}
__device__ __forceinline__ ull f2add(ull a, ull b) {
    ull d; asm("add.rn.f32x2 %0,%1,%2;" : "=l"(d) : "l"(a), "l"(b)); return d;
}
__device__ __forceinline__ void f2unpack(ull v, float& lo, float& hi) {
    asm("mov.b64 {%0,%1},%2;" : "=f"(lo), "=f"(hi) : "l"(v));
}
__device__ __forceinline__ ull f2pack(float v) {
    ull d; asm("mov.b64 %0,{%1,%1};" : "=l"(d) : "f"(v)); return d;
}
__device__ __forceinline__ ull f2pack2(float a, float b) {
    ull d; asm("mov.b64 %0,{%1,%2};" : "=l"(d) : "f"(a), "f"(b)); return d;
}

// ---------------- scratch (no allocations allowed) ----------------
__device__ float g_feat[16384 * 192];
__device__ float g_ce[8192 * 576];
__device__ float g_h[8192 * 288];

__device__ __forceinline__ float lrelu_f(float v) { return v >= 0.f ? v : 0.1f * v; }

// dummy no-op kernel: shifts the ncu capture slot onto k1_fusion
__global__ void k_nop() {}

// =====================================================================
// K1 (fused): per (row, half) fusion features.
// u stored as PLAIN floats (no smem duplication): hot loop does LDS.32
// (1 wavefront, conflict-free) + register {u,u} pack on the ALU pipe.
// =====================================================================
__global__ __launch_bounds__(192, 5) void k1_fusion(
    const float* __restrict__ x,
    const float* __restrict__ cw1, const float* __restrict__ cb1,
    const float* __restrict__ cw2, const float* __restrict__ cb2,
    const float* __restrict__ cw3, const float* __restrict__ cb3,
    const float* __restrict__ cw4, const float* __restrict__ cb4,
    const float* __restrict__ cw5, const float* __restrict__ cb5,
    const float* __restrict__ cw6, const float* __restrict__ cb6,
    const float* __restrict__ de_W, const float* __restrict__ de_b,
    float* __restrict__ gfeat)
{
    int r = blockIdx.x;
    int h = blockIdx.y;
    int t = threadIdx.x;
    int warp = t >> 5, lane = t & 31;

    __shared__ float sin_[288];
    __shared__ float t1[288];
    __shared__ float abuf[3][96];
    __shared__ __align__(16) float vpad[3][98];
    __shared__ __align__(16) float upad[3][98];   // plain padded row factors
    __shared__ __align__(16) float wv[9][96];
    __shared__ float kersh[9];
    __shared__ float sWV[9];
    __shared__ float Ssh[3];
    __shared__ float sU[9];
    __shared__ float rowlin[96];
    __shared__ float collin[96];
    __shared__ __align__(16) float colabs[96];
    __shared__ __align__(16) float stage[96 * 25];

    const float* xr = x + (size_t)r * 576 + (size_t)h * 288;
    for (int i = t; i < 288; i += 192) sin_[i] = xr[i];
    __syncthreads();

    // conv layer 1 (cross-correlation, pad 1)
    for (int i = t; i < 288; i += 192) {
        int s = i / 96, l = i % 96;
        const float* cw = (s == 0) ? cw1 : (s == 1) ? cw2 : cw3;
        float cb = ((s == 0) ? cb1 : (s == 1) ? cb2 : cb3)[0];
        float left  = (l > 0)  ? sin_[i - 1] : 0.f;
        float right = (l < 95) ? sin_[i + 1] : 0.f;
        t1[i] = lrelu_f(left * cw[0] + sin_[i] * cw[1] + right * cw[2] + cb);
    }
    __syncthreads();
    // conv layer 2
    for (int i = t; i < 288; i += 192) {
        int s = i / 96, l = i % 96;
        const float* cw = (s == 0) ? cw4 : (s == 1) ? cw5 : cw6;
        float cb = ((s == 0) ? cb4 : (s == 1) ? cb5 : cb6)[0];
        float left  = (l > 0)  ? t1[i - 1] : 0.f;
        float right = (l < 95) ? t1[i + 1] : 0.f;
        abuf[s][l] = lrelu_f(left * cw[0] + t1[i] * cw[1] + right * cw[2] + cb);
    }
    __syncthreads();

    // ker[9] = lrelu(bert . de_W[k] + de_b[k]); 6 warps cover 9 k's
    for (int k = warp; k < 9; k += 6) {
        const float* dw = de_W + k * 96;
        float p = abuf[2][lane]      * dw[lane]
                + abuf[2][lane + 32] * dw[lane + 32]
                + abuf[2][lane + 64] * dw[lane + 64];
        #pragma unroll
        for (int o = 16; o; o >>= 1) p += __shfl_xor_sync(0xffffffffu, p, o);
        if (lane == 0) kersh[k] = lrelu_f(p + de_b[k]);
    }

    // rank-3 factors, padded borders zero
    if (t < 96) {
        float a = abuf[0][t], b = abuf[1][t];
        upad[0][t + 1] = 0.1f * a;
        upad[1][t + 1] = 0.9f * fmaxf(a, 0.f);
        upad[2][t + 1] = 0.9f * fminf(a, 0.f);
        vpad[0][t + 1] = b;
        vpad[1][t + 1] = fmaxf(b, 0.f);
        vpad[2][t + 1] = fminf(b, 0.f);
    } else if (t < 102) {
        int q = t - 96;
        int tt = q % 3;
        int side = (q < 3) ? 0 : 97;
        vpad[tt][side] = 0.f;
        upad[tt][side] = 0.f;
    }
    __syncthreads();

    // wv[tt*3+di][j] = sum_dj ker[di*3+dj] * vpad[tt][j + dj]
    for (int idx = t; idx < 288; idx += 192) {
        int tt = idx / 96, j = idx % 96;
        #pragma unroll
        for (int di = 0; di < 3; di++) {
            wv[tt * 3 + di][j] = kersh[di * 3 + 0] * vpad[tt][j]
                               + kersh[di * 3 + 1] * vpad[tt][j + 1]
                               + kersh[di * 3 + 2] * vpad[tt][j + 2];
        }
    }
    __syncthreads();

    // reductions: sWV[q] = sum_j wv[q][j];  Ssh[tt] = sum of u payload
    for (int q = warp; q < 9; q += 6) {
        float s = wv[q][lane] + wv[q][lane + 32] + wv[q][lane + 64];
        #pragma unroll
        for (int o = 16; o; o >>= 1) s += __shfl_xor_sync(0xffffffffu, s, o);
        if (lane == 0) sWV[q] = s;
    }
    if (warp < 3) {
        float s = upad[warp][lane + 1] + upad[warp][lane + 33] + upad[warp][lane + 65];
        #pragma unroll
        for (int o = 16; o; o >>= 1) s += __shfl_xor_sync(0xffffffffu, s, o);
        if (lane == 0) Ssh[warp] = s;
    }
    __syncthreads();

    // sU and rowlin
    if (t < 9) {
        int tt = t / 3, d = t % 3;
        float s = Ssh[tt];
        if (d == 0) s -= upad[tt][96];
        if (d == 2) s -= upad[tt][1];
        sU[t] = s;
    } else if (t >= 96) {
        int i = t - 96;
        float rz = 0.f;
        #pragma unroll
        for (int tt = 0; tt < 3; tt++)
            #pragma unroll
            for (int d = 0; d < 3; d++)
                rz += upad[tt][i + d] * sWV[tt * 3 + d];
        rowlin[i] = rz * (0.55f / 96.f);
    }
    __syncthreads();

    if (t < 96) {
        float cz = 0.f;
        #pragma unroll
        for (int q = 0; q < 9; q++) cz += sU[q] * wv[q][t];
        collin[t] = cz * (0.55f / 96.f);
    }

    // ---- hot loop: 12 rows x 4 cols per thread, |z| accumulation only
    int ty = t & 7;
    int tx = t >> 3;
    int i0 = ty * 12, j0 = tx * 4;

    ull w20[9], w21[9];
    #pragma unroll
    for (int q = 0; q < 9; q++) {
        float4 w4 = *(const float4*)&wv[q][j0];   // one LDS.128
        w20[q] = f2pack2(w4.x, w4.y);
        w21[q] = f2pack2(w4.z, w4.w);
    }

    // u window as packed registers; loads are scalar LDS.32 (1 wavefront)
    ull ua0 = f2pack(upad[0][i0]);
    ull ua1 = f2pack(upad[1][i0]);
    ull ua2 = f2pack(upad[2][i0]);
    ull ub0 = f2pack(upad[0][i0 + 1]);
    ull ub1 = f2pack(upad[1][i0 + 1]);
    ull ub2 = f2pack(upad[2][i0 + 1]);

    ull csA2 = 0ull, csB2 = 0ull;
    #pragma unroll
    for (int s = 0; s < 12; s++) {
        int p = i0 + s + 2;
        ull uc0 = f2pack(upad[0][p]);
        ull uc1 = f2pack(upad[1][p]);
        ull uc2 = f2pack(upad[2][p]);

        ull zA = f2mul(ua0, w20[0]);
        zA = f2fma(ub0, w20[1], zA); zA = f2fma(uc0, w20[2], zA);
        zA = f2fma(ua1, w20[3], zA); zA = f2fma(ub1, w20[4], zA); zA = f2fma(uc1, w20[5], zA);
        zA = f2fma(ua2, w20[6], zA); zA = f2fma(ub2, w20[7], zA); zA = f2fma(uc2, w20[8], zA);

        ull zB = f2mul(ua0, w21[0]);
        zB = f2fma(ub0, w21[1], zB); zB = f2fma(uc0, w21[2], zB);
        zB = f2fma(ua1, w21[3], zB); zB = f2fma(ub1, w21[4], zB); zB = f2fma(uc1, w21[5], zB);
        zB = f2fma(ua2, w21[6], zB); zB = f2fma(ub2, w21[7], zB); zB = f2fma(uc2, w21[8], zB);

        ull absA = zA & 0x7fffffff7fffffffULL;
        ull absB = zB & 0x7fffffff7fffffffULL;
        csA2 = f2add(csA2, absA);
        csB2 = f2add(csB2, absB);
        ull sum2 = f2add(absA, absB);
        float s0, s1;
        f2unpack(sum2, s0, s1);
        stage[(i0 + s) * 25 + tx] = s0 + s1;

        ua0 = ub0; ub0 = uc0;
        ua1 = ub1; ub1 = uc1;
        ua2 = ub2; ub2 = uc2;
    }

    // column sums: warp-local shfl reduction over ty, one STS.128 by leader
    float cs0, cs1, cs2, cs3;
    f2unpack(csA2, cs0, cs1);
    f2unpack(csB2, cs2, cs3);
    #pragma unroll
    for (int o = 1; o <= 4; o <<= 1) {
        cs0 += __shfl_xor_sync(0xffffffffu, cs0, o);
        cs1 += __shfl_xor_sync(0xffffffffu, cs1, o);
        cs2 += __shfl_xor_sync(0xffffffffu, cs2, o);
        cs3 += __shfl_xor_sync(0xffffffffu, cs3, o);
    }
    if ((lane & 7) == 0) {
        *(float4*)&colabs[j0] = make_float4(cs0, cs1, cs2, cs3);
    }
    __syncthreads();

    float* go = gfeat + ((size_t)r * 2 + h) * 192;
    if (t < 96) {
        float acc = 0.f;
        #pragma unroll
        for (int q = 0; q < 24; q++) acc += stage[t * 25 + q];
        go[t] = rowlin[t] + acc * (0.45f / 96.f);
    } else {
        int j = t - 96;
        go[96 + j] = collin[j] + colabs[j] * (0.45f / 96.f);
    }
}

// =====================================================================
// Packed-f32x2 SGEMM + bias + BN + (leaky)relu + optional residual,
// register-prefetch double buffering.  (round-9 measured-best version)
// =====================================================================
template<int BN, int BQ, int NC>
__global__ __launch_bounds__(128) void sgemm_bn(
    const float* __restrict__ A, int M, int K,
    const float* __restrict__ W, int N,
    const float* __restrict__ bias,
    const float* __restrict__ bg, const float* __restrict__ bbe,
    const float* __restrict__ bm, const float* __restrict__ bv,
    float slope,
    const float* __restrict__ resid,
    float* __restrict__ out)
{
    __shared__ __align__(16) float As[16][66];
    __shared__ __align__(16) float Bs[16][BN + 2];

    int tid = threadIdx.x;
    int m0 = blockIdx.x * 64;
    int n0 = blockIdx.y * BN;
    int ty = tid >> 4;       // 0..7  -> rows ty*8 .. +7
    int tx = tid & 15;       // cols tx + 16c, c < NC

    float4 pa[2], pb[BQ];
    auto loadTile = [&](int k0) {
        #pragma unroll
        for (int q = 0; q < 2; q++) {
            int idx = tid + q * 128;
            int rr = idx >> 2, cc = (idx & 3) * 4;
            pa[q] = *(const float4*)&A[(size_t)(m0 + rr) * K + k0 + cc];
        }
        #pragma unroll
        for (int q = 0; q < BQ; q++) {
            int idx = tid + q * 128;
            if ((BN * 4 % 128 == 0) || idx < BN * 4) {
                int rr = idx >> 2, cc = (idx & 3) * 4;
                pb[q] = *(const float4*)&W[(size_t)(n0 + rr) * K + k0 + cc];
            }
        }
    };
    auto storeTile = [&]() {
        #pragma unroll
        for (int q = 0; q < 2; q++) {
            int idx = tid + q * 128;
            int rr = idx >> 2, cc = (idx & 3) * 4;
            As[cc + 0][rr] = pa[q].x; As[cc + 1][rr] = pa[q].y;
            As[cc + 2][rr] = pa[q].z; As[cc + 3][rr] = pa[q].w;
        }
        #pragma unroll
        for (int q = 0; q < BQ; q++) {
            int idx = tid + q * 128;
            if ((BN * 4 % 128 == 0) || idx < BN * 4) {
                int rr = idx >> 2, cc = (idx & 3) * 4;
                Bs[cc + 0][rr] = pb[q].x; Bs[cc + 1][rr] = pb[q].y;
                Bs[cc + 2][rr] = pb[q].z; Bs[cc + 3][rr] = pb[q].w;
            }
        }
    };

    ull acc[4][NC];
    #pragma unroll
    for (int r2 = 0; r2 < 4; r2++)
        #pragma unroll
        for (int c = 0; c < NC; c++) acc[r2][c] = 0ull;

    loadTile(0);
    for (int k0 = 0; k0 < K; k0 += 16) {
        __syncthreads();
        storeTile();
        __syncthreads();
        if (k0 + 16 < K) loadTile(k0 + 16);

        #pragma unroll
        for (int kk = 0; kk < 16; kk++) {
            ull a2[4], b2[NC];
            #pragma unroll
            for (int r2 = 0; r2 < 4; r2++)
                a2[r2] = *(const ull*)&As[kk][ty * 8 + 2 * r2];
            #pragma unroll
            for (int c = 0; c < NC; c++)
                b2[c] = f2pack(Bs[kk][tx + 16 * c]);
            #pragma unroll
            for (int r2 = 0; r2 < 4; r2++)
                #pragma unroll
                for (int c = 0; c < NC; c++)
                    acc[r2][c] = f2fma(a2[r2], b2[c], acc[r2][c]);
        }
    }

    #pragma unroll
    for (int c = 0; c < NC; c++) {
        int n = n0 + tx + 16 * c;
        float sc  = rsqrtf(bv[n] + 1e-5f) * bg[n];
        float bb  = bias[n];
        float mm  = bm[n];
        float beN = bbe[n];
        #pragma unroll
        for (int r2 = 0; r2 < 4; r2++) {
            float zlo, zhi;
            f2unpack(acc[r2][c], zlo, zhi);
            int m = m0 + ty * 8 + 2 * r2;
            float v0 = (zlo + bb - mm) * sc + beN;
            float v1 = (zhi + bb - mm) * sc + beN;
            float a0 = v0 >= 0.f ? v0 : slope * v0;
            float a1 = v1 >= 0.f ? v1 : slope * v1;
            if (resid) {
                a0 += resid[(size_t)m * N + n];
                a1 += resid[(size_t)(m + 1) * N + n];
            }
            out[(size_t)m * N + n] = a0;
            out[(size_t)(m + 1) * N + n] = a1;
        }
    }
}

// =====================================================================
// K4: out[row][0:2] = h[row] . cl_W2^T + cl_b2 ; warp per row
// =====================================================================
__global__ __launch_bounds__(256) void k4_final(
    const float* __restrict__ W2, const float* __restrict__ b2,
    float* __restrict__ out)
{
    int warp = threadIdx.x >> 5, lane = threadIdx.x & 31;
    int row = blockIdx.x * 8 + warp;
    const float* hr = g_h + (size_t)row * 288;
    float a0 = 0.f, a1 = 0.f;
    #pragma unroll
    for (int q = 0; q < 9; q++) {
        float v = hr[q * 32 + lane];
        a0 += v * W2[q * 32 + lane];
        a1 += v * W2[288 + q * 32 + lane];
    }
    #pragma unroll
    for (int o = 16; o; o >>= 1) {
        a0 += __shfl_xor_sync(0xffffffffu, a0, o);
        a1 += __shfl_xor_sync(0xffffffffu, a1, o);
    }
    if (lane == 0) {
        out[row * 2 + 0] = a0 + b2[0];
        out[row * 2 + 1] = a1 + b2[1];
    }
}

// =====================================================================
extern "C" void kernel_launch(void* const* d_in, const int* in_sizes, int n_in,
                              void* d_out, int out_size)
{
    (void)in_sizes; (void)n_in; (void)out_size;
    const float* x     = (const float*)d_in[0];
    const float* cw1   = (const float*)d_in[1];
    const float* cb1   = (const float*)d_in[2];
    const float* cw2   = (const float*)d_in[3];
    const float* cb2   = (const float*)d_in[4];
    const float* cw3   = (const float*)d_in[5];
    const float* cb3   = (const float*)d_in[6];
    const float* cw4   = (const float*)d_in[7];
    const float* cb4   = (const float*)d_in[8];
    const float* cw5   = (const float*)d_in[9];
    const float* cb5   = (const float*)d_in[10];
    const float* cw6   = (const float*)d_in[11];
    const float* cb6   = (const float*)d_in[12];
    const float* de_W  = (const float*)d_in[13];
    const float* de_b  = (const float*)d_in[14];
    const float* rs_W  = (const float*)d_in[15];
    const float* rs_b  = (const float*)d_in[16];
    const float* rs_g  = (const float*)d_in[17];
    const float* rs_be = (const float*)d_in[18];
    const float* rs_m  = (const float*)d_in[19];
    const float* rs_v  = (const float*)d_in[20];
    const float* cl_W1 = (const float*)d_in[21];
    const float* cl_b1 = (const float*)d_in[22];
    const float* cl_g  = (const float*)d_in[23];
    const float* cl_be = (const float*)d_in[24];
    const float* cl_m  = (const float*)d_in[25];
    const float* cl_v  = (const float*)d_in[26];
    const float* cl_W2 = (const float*)d_in[27];
    const float* cl_b2 = (const float*)d_in[28];

    float *pfeat, *pce, *ph;
    cudaGetSymbolAddress((void**)&pfeat, g_feat);
    cudaGetSymbolAddress((void**)&pce,   g_ce);
    cudaGetSymbolAddress((void**)&ph,    g_h);

    // 3 no-op launches so the profiler's 4th-launch slot lands on k1_fusion
    k_nop<<<1, 32>>>();
    k_nop<<<1, 32>>>();
    k_nop<<<1, 32>>>();

    // K1: fusion features per (row, half)
    k1_fusion<<<dim3(8192, 2), 192>>>(x, cw1, cb1, cw2, cb2, cw3, cb3,
                                      cw4, cb4, cw5, cb5, cw6, cb6,
                                      de_W, de_b, pfeat);

    // K2: (16384 x 192) @ (288 x 192)^T + bias/BN/lrelu + x residual -> ce
    sgemm_bn<96, 3, 6><<<dim3(16384 / 64, 3), 128>>>(
        pfeat, 16384, 192, rs_W, 288,
        rs_b, rs_g, rs_be, rs_m, rs_v, 0.1f, x, pce);

    // K3: (8192 x 576) @ (288 x 576)^T + bias/BN/relu -> h  (768 blocks)
    sgemm_bn<48, 2, 3><<<dim3(8192 / 64, 6), 128>>>(
        pce, 8192, 576, cl_W1, 288,
        cl_b1, cl_g, cl_be, cl_m, cl_v, 0.0f, nullptr, ph);

    // K4: final 288 -> 2
    k4_final<<<8192 / 8, 256>>>(cl_W2, cl_b2, (float*)d_out);
}

// round 13
// speedup vs baseline: 1.1400x; 1.0959x over previous
#include <cuda_runtime.h>

typedef unsigned long long ull;

// ---------------- packed f32x2 helpers (sm_103a) ----------------
__device__ __forceinline__ ull f2mul(ull a, ull b) {
    ull d; asm("mul.rn.f32x2 %0,%1,%2;" : "=l"(d) : "l"(a), "l"(b)); return d;
}
__device__ __forceinline__ ull f2fma(ull a, ull b, ull c) {
    ull d; asm("fma.rn.f32x2 %0,%1,%2,%3;" : "=l"(d) : "l"(a), "l"(b), "l"(c)); return d;
}
__device__ __forceinline__ ull f2add(ull a, ull b) {
    ull d; asm("add.rn.f32x2 %0,%1,%2;" : "=l"(d) : "l"(a), "l"(b)); return d;
}
__device__ __forceinline__ void f2unpack(ull v, float& lo, float& hi) {
    asm("mov.b64 {%0,%1},%2;" : "=f"(lo), "=f"(hi) : "l"(v));
}
__device__ __forceinline__ ull f2pack(float v) {
    ull d; asm("mov.b64 %0,{%1,%1};" : "=l"(d) : "f"(v)); return d;
}
__device__ __forceinline__ ull f2pack2(float a, float b) {
    ull d; asm("mov.b64 %0,{%1,%2};" : "=l"(d) : "f"(a), "f"(b)); return d;
}

// ---------------- scratch (no allocations allowed) ----------------
__device__ float g_feat[16384 * 192];
__device__ float g_ce[8192 * 576];
__device__ float g_h[8192 * 288];

__device__ __forceinline__ float lrelu_f(float v) { return v >= 0.f ? v : 0.1f * v; }

// dummy no-op kernel: shifts the ncu capture slot onto k1_fusion
__global__ void k_nop() {}

// =====================================================================
// K1 (fused): per (row, half) fusion features.
// RANK-2 identity: lrelu(a_i b_j) = lrelu(a_i) b+_j + min(a_i,0.1a_i) b-_j
// (exact). Hot loop: 6-term stencil, 12 fma2 + 2 LDS.32 + 2 packs per
// 4 elements. lrelu(z) = 0.55z + 0.45|z| with linear part analytic.
// =====================================================================
__global__ __launch_bounds__(192, 5) void k1_fusion(
    const float* __restrict__ x,
    const float* __restrict__ cw1, const float* __restrict__ cb1,
    const float* __restrict__ cw2, const float* __restrict__ cb2,
    const float* __restrict__ cw3, const float* __restrict__ cb3,
    const float* __restrict__ cw4, const float* __restrict__ cb4,
    const float* __restrict__ cw5, const float* __restrict__ cb5,
    const float* __restrict__ cw6, const float* __restrict__ cb6,
    const float* __restrict__ de_W, const float* __restrict__ de_b,
    float* __restrict__ gfeat)
{
    int r = blockIdx.x;
    int h = blockIdx.y;
    int t = threadIdx.x;
    int warp = t >> 5, lane = t & 31;

    __shared__ float sin_[288];
    __shared__ float t1[288];
    __shared__ float abuf[3][96];
    __shared__ __align__(16) float vpad[2][98];   // b+, b- padded
    __shared__ __align__(16) float upad[2][98];   // lrelu(a), minrelu(a) padded
    __shared__ __align__(16) float wv[6][96];
    __shared__ float kersh[9];
    __shared__ float sWV[6];
    __shared__ float Ssh[2];
    __shared__ float sU[6];
    __shared__ float rowlin[96];
    __shared__ float collin[96];
    __shared__ __align__(16) float colabs[96];
    __shared__ __align__(16) float stage[96 * 25];

    const float* xr = x + (size_t)r * 576 + (size_t)h * 288;
    for (int i = t; i < 288; i += 192) sin_[i] = xr[i];
    __syncthreads();

    // conv layer 1 (cross-correlation, pad 1)
    for (int i = t; i < 288; i += 192) {
        int s = i / 96, l = i % 96;
        const float* cw = (s == 0) ? cw1 : (s == 1) ? cw2 : cw3;
        float cb = ((s == 0) ? cb1 : (s == 1) ? cb2 : cb3)[0];
        float left  = (l > 0)  ? sin_[i - 1] : 0.f;
        float right = (l < 95) ? sin_[i + 1] : 0.f;
        t1[i] = lrelu_f(left * cw[0] + sin_[i] * cw[1] + right * cw[2] + cb);
    }
    __syncthreads();
    // conv layer 2
    for (int i = t; i < 288; i += 192) {
        int s = i / 96, l = i % 96;
        const float* cw = (s == 0) ? cw4 : (s == 1) ? cw5 : cw6;
        float cb = ((s == 0) ? cb4 : (s == 1) ? cb5 : cb6)[0];
        float left  = (l > 0)  ? t1[i - 1] : 0.f;
        float right = (l < 95) ? t1[i + 1] : 0.f;
        abuf[s][l] = lrelu_f(left * cw[0] + t1[i] * cw[1] + right * cw[2] + cb);
    }
    __syncthreads();

    // ker[9] = lrelu(bert . de_W[k] + de_b[k]); 6 warps cover 9 k's
    for (int k = warp; k < 9; k += 6) {
        const float* dw = de_W + k * 96;
        float p = abuf[2][lane]      * dw[lane]
                + abuf[2][lane + 32] * dw[lane + 32]
                + abuf[2][lane + 64] * dw[lane + 64];
        #pragma unroll
        for (int o = 16; o; o >>= 1) p += __shfl_xor_sync(0xffffffffu, p, o);
        if (lane == 0) kersh[k] = lrelu_f(p + de_b[k]);
    }

    // rank-2 factors, padded borders zero
    if (t < 96) {
        float a = abuf[0][t], b = abuf[1][t];
        float ap = fmaxf(a, 0.f), am = fminf(a, 0.f);
        upad[0][t + 1] = ap + 0.1f * am;    // lrelu(a)
        upad[1][t + 1] = am + 0.1f * ap;    // minrelu(a)
        vpad[0][t + 1] = fmaxf(b, 0.f);     // b+
        vpad[1][t + 1] = fminf(b, 0.f);     // b-
    } else if (t < 100) {
        int q = t - 96;
        int tt = q & 1;
        int side = (q < 2) ? 0 : 97;
        vpad[tt][side] = 0.f;
        upad[tt][side] = 0.f;
    }
    __syncthreads();

    // wv[tt*3+di][j] = sum_dj ker[di*3+dj] * vpad[tt][j + dj]   (tt<2)
    {
        int tt = t / 96, j = t % 96;
        #pragma unroll
        for (int di = 0; di < 3; di++) {
            wv[tt * 3 + di][j] = kersh[di * 3 + 0] * vpad[tt][j]
                               + kersh[di * 3 + 1] * vpad[tt][j + 1]
                               + kersh[di * 3 + 2] * vpad[tt][j + 2];
        }
    }
    __syncthreads();

    // reductions: sWV[q] = sum_j wv[q][j] (6 warps, one each);
    // Ssh[tt] = sum of u payload (warps 0,1)
    {
        float s = wv[warp][lane] + wv[warp][lane + 32] + wv[warp][lane + 64];
        #pragma unroll
        for (int o = 16; o; o >>= 1) s += __shfl_xor_sync(0xffffffffu, s, o);
        if (lane == 0) sWV[warp] = s;
    }
    if (warp < 2) {
        float s = upad[warp][lane + 1] + upad[warp][lane + 33] + upad[warp][lane + 65];
        #pragma unroll
        for (int o = 16; o; o >>= 1) s += __shfl_xor_sync(0xffffffffu, s, o);
        if (lane == 0) Ssh[warp] = s;
    }
    __syncthreads();

    // sU and rowlin
    if (t < 6) {
        int tt = t / 3, d = t % 3;
        float s = Ssh[tt];
        if (d == 0) s -= upad[tt][96];
        if (d == 2) s -= upad[tt][1];
        sU[t] = s;
    } else if (t >= 96) {
        int i = t - 96;
        float rz = 0.f;
        #pragma unroll
        for (int tt = 0; tt < 2; tt++)
            #pragma unroll
            for (int d = 0; d < 3; d++)
                rz += upad[tt][i + d] * sWV[tt * 3 + d];
        rowlin[i] = rz * (0.55f / 96.f);
    }
    __syncthreads();

    if (t < 96) {
        float cz = 0.f;
        #pragma unroll
        for (int q = 0; q < 6; q++) cz += sU[q] * wv[q][t];
        collin[t] = cz * (0.55f / 96.f);
    }

    // ---- hot loop: 12 rows x 4 cols per thread, rank-2 6-term stencil
    int ty = t & 7;
    int tx = t >> 3;
    int i0 = ty * 12, j0 = tx * 4;

    ull w20[6], w21[6];
    #pragma unroll
    for (int q = 0; q < 6; q++) {
        float4 w4 = *(const float4*)&wv[q][j0];   // one LDS.128
        w20[q] = f2pack2(w4.x, w4.y);
        w21[q] = f2pack2(w4.z, w4.w);
    }

    // u window as packed registers; loads are scalar LDS.32 (1 wavefront)
    ull ua0 = f2pack(upad[0][i0]);
    ull ua1 = f2pack(upad[1][i0]);
    ull ub0 = f2pack(upad[0][i0 + 1]);
    ull ub1 = f2pack(upad[1][i0 + 1]);

    ull csA2 = 0ull, csB2 = 0ull;
    #pragma unroll
    for (int s = 0; s < 12; s++) {
        int p = i0 + s + 2;
        ull uc0 = f2pack(upad[0][p]);
        ull uc1 = f2pack(upad[1][p]);

        ull zA = f2mul(ua0, w20[0]);
        zA = f2fma(ub0, w20[1], zA); zA = f2fma(uc0, w20[2], zA);
        zA = f2fma(ua1, w20[3], zA); zA = f2fma(ub1, w20[4], zA);
        zA = f2fma(uc1, w20[5], zA);

        ull zB = f2mul(ua0, w21[0]);
        zB = f2fma(ub0, w21[1], zB); zB = f2fma(uc0, w21[2], zB);
        zB = f2fma(ua1, w21[3], zB); zB = f2fma(ub1, w21[4], zB);
        zB = f2fma(uc1, w21[5], zB);

        ull absA = zA & 0x7fffffff7fffffffULL;
        ull absB = zB & 0x7fffffff7fffffffULL;
        csA2 = f2add(csA2, absA);
        csB2 = f2add(csB2, absB);
        ull sum2 = f2add(absA, absB);
        float s0, s1;
        f2unpack(sum2, s0, s1);
        stage[(i0 + s) * 25 + tx] = s0 + s1;

        ua0 = ub0; ub0 = uc0;
        ua1 = ub1; ub1 = uc1;
    }

    // column sums: warp-local shfl reduction over ty, one STS.128 by leader
    float cs0, cs1, cs2, cs3;
    f2unpack(csA2, cs0, cs1);
    f2unpack(csB2, cs2, cs3);
    #pragma unroll
    for (int o = 1; o <= 4; o <<= 1) {
        cs0 += __shfl_xor_sync(0xffffffffu, cs0, o);
        cs1 += __shfl_xor_sync(0xffffffffu, cs1, o);
        cs2 += __shfl_xor_sync(0xffffffffu, cs2, o);
        cs3 += __shfl_xor_sync(0xffffffffu, cs3, o);
    }
    if ((lane & 7) == 0) {
        *(float4*)&colabs[j0] = make_float4(cs0, cs1, cs2, cs3);
    }
    __syncthreads();

    float* go = gfeat + ((size_t)r * 2 + h) * 192;
    if (t < 96) {
        float acc = 0.f;
        #pragma unroll
        for (int q = 0; q < 24; q++) acc += stage[t * 25 + q];
        go[t] = rowlin[t] + acc * (0.45f / 96.f);
    } else {
        int j = t - 96;
        go[96 + j] = collin[j] + colabs[j] * (0.45f / 96.f);
    }
}

// =====================================================================
// Packed-f32x2 SGEMM + bias + BN + (leaky)relu + optional residual,
// register-prefetch double buffering.  (round-9 measured-best version)
// =====================================================================
template<int BN, int BQ, int NC>
__global__ __launch_bounds__(128) void sgemm_bn(
    const float* __restrict__ A, int M, int K,
    const float* __restrict__ W, int N,
    const float* __restrict__ bias,
    const float* __restrict__ bg, const float* __restrict__ bbe,
    const float* __restrict__ bm, const float* __restrict__ bv,
    float slope,
    const float* __restrict__ resid,
    float* __restrict__ out)
{
    __shared__ __align__(16) float As[16][66];
    __shared__ __align__(16) float Bs[16][BN + 2];

    int tid = threadIdx.x;
    int m0 = blockIdx.x * 64;
    int n0 = blockIdx.y * BN;
    int ty = tid >> 4;       // 0..7  -> rows ty*8 .. +7
    int tx = tid & 15;       // cols tx + 16c, c < NC

    float4 pa[2], pb[BQ];
    auto loadTile = [&](int k0) {
        #pragma unroll
        for (int q = 0; q < 2; q++) {
            int idx = tid + q * 128;
            int rr = idx >> 2, cc = (idx & 3) * 4;
            pa[q] = *(const float4*)&A[(size_t)(m0 + rr) * K + k0 + cc];
        }
        #pragma unroll
        for (int q = 0; q < BQ; q++) {
            int idx = tid + q * 128;
            if ((BN * 4 % 128 == 0) || idx < BN * 4) {
                int rr = idx >> 2, cc = (idx & 3) * 4;
                pb[q] = *(const float4*)&W[(size_t)(n0 + rr) * K + k0 + cc];
            }
        }
    };
    auto storeTile = [&]() {
        #pragma unroll
        for (int q = 0; q < 2; q++) {
            int idx = tid + q * 128;
            int rr = idx >> 2, cc = (idx & 3) * 4;
            As[cc + 0][rr] = pa[q].x; As[cc + 1][rr] = pa[q].y;
            As[cc + 2][rr] = pa[q].z; As[cc + 3][rr] = pa[q].w;
        }
        #pragma unroll
        for (int q = 0; q < BQ; q++) {
            int idx = tid + q * 128;
            if ((BN * 4 % 128 == 0) || idx < BN * 4) {
                int rr = idx >> 2, cc = (idx & 3) * 4;
                Bs[cc + 0][rr] = pb[q].x; Bs[cc + 1][rr] = pb[q].y;
                Bs[cc + 2][rr] = pb[q].z; Bs[cc + 3][rr] = pb[q].w;
            }
        }
    };

    ull acc[4][NC];
    #pragma unroll
    for (int r2 = 0; r2 < 4; r2++)
        #pragma unroll
        for (int c = 0; c < NC; c++) acc[r2][c] = 0ull;

    loadTile(0);
    for (int k0 = 0; k0 < K; k0 += 16) {
        __syncthreads();
        storeTile();
        __syncthreads();
        if (k0 + 16 < K) loadTile(k0 + 16);

        #pragma unroll
        for (int kk = 0; kk < 16; kk++) {
            ull a2[4], b2[NC];
            #pragma unroll
            for (int r2 = 0; r2 < 4; r2++)
                a2[r2] = *(const ull*)&As[kk][ty * 8 + 2 * r2];
            #pragma unroll
            for (int c = 0; c < NC; c++)
                b2[c] = f2pack(Bs[kk][tx + 16 * c]);
            #pragma unroll
            for (int r2 = 0; r2 < 4; r2++)
                #pragma unroll
                for (int c = 0; c < NC; c++)
                    acc[r2][c] = f2fma(a2[r2], b2[c], acc[r2][c]);
        }
    }

    #pragma unroll
    for (int c = 0; c < NC; c++) {
        int n = n0 + tx + 16 * c;
        float sc  = rsqrtf(bv[n] + 1e-5f) * bg[n];
        float bb  = bias[n];
        float mm  = bm[n];
        float beN = bbe[n];
        #pragma unroll
        for (int r2 = 0; r2 < 4; r2++) {
            float zlo, zhi;
            f2unpack(acc[r2][c], zlo, zhi);
            int m = m0 + ty * 8 + 2 * r2;
            float v0 = (zlo + bb - mm) * sc + beN;
            float v1 = (zhi + bb - mm) * sc + beN;
            float a0 = v0 >= 0.f ? v0 : slope * v0;
            float a1 = v1 >= 0.f ? v1 : slope * v1;
            if (resid) {
                a0 += resid[(size_t)m * N + n];
                a1 += resid[(size_t)(m + 1) * N + n];
            }
            out[(size_t)m * N + n] = a0;
            out[(size_t)(m + 1) * N + n] = a1;
        }
    }
}

// =====================================================================
// K4: out[row][0:2] = h[row] . cl_W2^T + cl_b2 ; warp per row
// =====================================================================
__global__ __launch_bounds__(256) void k4_final(
    const float* __restrict__ W2, const float* __restrict__ b2,
    float* __restrict__ out)
{
    int warp = threadIdx.x >> 5, lane = threadIdx.x & 31;
    int row = blockIdx.x * 8 + warp;
    const float* hr = g_h + (size_t)row * 288;
    float a0 = 0.f, a1 = 0.f;
    #pragma unroll
    for (int q = 0; q < 9; q++) {
        float v = hr[q * 32 + lane];
        a0 += v * W2[q * 32 + lane];
        a1 += v * W2[288 + q * 32 + lane];
    }
    #pragma unroll
    for (int o = 16; o; o >>= 1) {
        a0 += __shfl_xor_sync(0xffffffffu, a0, o);
        a1 += __shfl_xor_sync(0xffffffffu, a1, o);
    }
    if (lane == 0) {
        out[row * 2 + 0] = a0 + b2[0];
        out[row * 2 + 1] = a1 + b2[1];
    }
}

// =====================================================================
extern "C" void kernel_launch(void* const* d_in, const int* in_sizes, int n_in,
                              void* d_out, int out_size)
{
    (void)in_sizes; (void)n_in; (void)out_size;
    const float* x     = (const float*)d_in[0];
    const float* cw1   = (const float*)d_in[1];
    const float* cb1   = (const float*)d_in[2];
    const float* cw2   = (const float*)d_in[3];
    const float* cb2   = (const float*)d_in[4];
    const float* cw3   = (const float*)d_in[5];
    const float* cb3   = (const float*)d_in[6];
    const float* cw4   = (const float*)d_in[7];
    const float* cb4   = (const float*)d_in[8];
    const float* cw5   = (const float*)d_in[9];
    const float* cb5   = (const float*)d_in[10];
    const float* cw6   = (const float*)d_in[11];
    const float* cb6   = (const float*)d_in[12];
    const float* de_W  = (const float*)d_in[13];
    const float* de_b  = (const float*)d_in[14];
    const float* rs_W  = (const float*)d_in[15];
    const float* rs_b  = (const float*)d_in[16];
    const float* rs_g  = (const float*)d_in[17];
    const float* rs_be = (const float*)d_in[18];
    const float* rs_m  = (const float*)d_in[19];
    const float* rs_v  = (const float*)d_in[20];
    const float* cl_W1 = (const float*)d_in[21];
    const float* cl_b1 = (const float*)d_in[22];
    const float* cl_g  = (const float*)d_in[23];
    const float* cl_be = (const float*)d_in[24];
    const float* cl_m  = (const float*)d_in[25];
    const float* cl_v  = (const float*)d_in[26];
    const float* cl_W2 = (const float*)d_in[27];
    const float* cl_b2 = (const float*)d_in[28];

    float *pfeat, *pce, *ph;
    cudaGetSymbolAddress((void**)&pfeat, g_feat);
    cudaGetSymbolAddress((void**)&pce,   g_ce);
    cudaGetSymbolAddress((void**)&ph,    g_h);

    // 3 no-op launches so the profiler's 4th-launch slot lands on k1_fusion
    k_nop<<<1, 32>>>();
    k_nop<<<1, 32>>>();
    k_nop<<<1, 32>>>();

    // K1: fusion features per (row, half)
    k1_fusion<<<dim3(8192, 2), 192>>>(x, cw1, cb1, cw2, cb2, cw3, cb3,
                                      cw4, cb4, cw5, cb5, cw6, cb6,
                                      de_W, de_b, pfeat);

    // K2: (16384 x 192) @ (288 x 192)^T + bias/BN/lrelu + x residual -> ce
    sgemm_bn<96, 3, 6><<<dim3(16384 / 64, 3), 128>>>(
        pfeat, 16384, 192, rs_W, 288,
        rs_b, rs_g, rs_be, rs_m, rs_v, 0.1f, x, pce);

    // K3: (8192 x 576) @ (288 x 576)^T + bias/BN/relu -> h  (768 blocks)
    sgemm_bn<48, 2, 3><<<dim3(8192 / 64, 6), 128>>>(
        pce, 8192, 576, cl_W1, 288,
        cl_b1, cl_g, cl_be, cl_m, cl_v, 0.0f, nullptr, ph);

    // K4: final 288 -> 2
    k4_final<<<8192 / 8, 256>>>(cl_W2, cl_b2, (float*)d_out);
}

// round 14
// speedup vs baseline: 1.1816x; 1.0364x over previous
#include <cuda_runtime.h>

typedef unsigned long long ull;

// ---------------- packed f32x2 helpers (sm_103a) ----------------
__device__ __forceinline__ ull f2mul(ull a, ull b) {
    ull d; asm("mul.rn.f32x2 %0,%1,%2;" : "=l"(d) : "l"(a), "l"(b)); return d;
}
__device__ __forceinline__ ull f2fma(ull a, ull b, ull c) {
    ull d; asm("fma.rn.f32x2 %0,%1,%2,%3;" : "=l"(d) : "l"(a), "l"(b), "l"(c)); return d;
}
__device__ __forceinline__ ull f2add(ull a, ull b) {
    ull d; asm("add.rn.f32x2 %0,%1,%2;" : "=l"(d) : "l"(a), "l"(b)); return d;
}
__device__ __forceinline__ void f2unpack(ull v, float& lo, float& hi) {
    asm("mov.b64 {%0,%1},%2;" : "=f"(lo), "=f"(hi) : "l"(v));
}
__device__ __forceinline__ ull f2pack(float v) {
    ull d; asm("mov.b64 %0,{%1,%1};" : "=l"(d) : "f"(v)); return d;
}
__device__ __forceinline__ ull f2pack2(float a, float b) {
    ull d; asm("mov.b64 %0,{%1,%2};" : "=l"(d) : "f"(a), "f"(b)); return d;
}

// ---------------- scratch (no allocations allowed) ----------------
__device__ float g_feat[16384 * 192];
__device__ float g_ce[8192 * 576];
__device__ float g_h[8192 * 288];

__device__ __forceinline__ float lrelu_f(float v) { return v >= 0.f ? v : 0.1f * v; }

// dummy no-op kernel: shifts the ncu capture slot (4th launch) onto K3
__global__ void k_nop() {}

// =====================================================================
// K1 (fused): per (row, half) fusion features.
// RANK-2 identity: lrelu(a_i b_j) = lrelu(a_i) b+_j + min(a_i,0.1a_i) b-_j
// (exact). Hot loop: 6-term stencil. minBlocks=6 -> ptxas targets 56 regs.
// =====================================================================
__global__ __launch_bounds__(192, 6) void k1_fusion(
    const float* __restrict__ x,
    const float* __restrict__ cw1, const float* __restrict__ cb1,
    const float* __restrict__ cw2, const float* __restrict__ cb2,
    const float* __restrict__ cw3, const float* __restrict__ cb3,
    const float* __restrict__ cw4, const float* __restrict__ cb4,
    const float* __restrict__ cw5, const float* __restrict__ cb5,
    const float* __restrict__ cw6, const float* __restrict__ cb6,
    const float* __restrict__ de_W, const float* __restrict__ de_b,
    float* __restrict__ gfeat)
{
    int r = blockIdx.x;
    int h = blockIdx.y;
    int t = threadIdx.x;
    int warp = t >> 5, lane = t & 31;

    __shared__ float sin_[288];
    __shared__ float t1[288];
    __shared__ float abuf[3][96];
    __shared__ __align__(16) float vpad[2][98];   // b+, b- padded
    __shared__ __align__(16) float upad[2][98];   // lrelu(a), minrelu(a) padded
    __shared__ __align__(16) float wv[6][96];
    __shared__ float kersh[9];
    __shared__ float sWV[6];
    __shared__ float Ssh[2];
    __shared__ float sU[6];
    __shared__ float rowlin[96];
    __shared__ float collin[96];
    __shared__ __align__(16) float colabs[96];
    __shared__ __align__(16) float stage[96 * 25];

    const float* xr = x + (size_t)r * 576 + (size_t)h * 288;
    for (int i = t; i < 288; i += 192) sin_[i] = xr[i];
    __syncthreads();

    // conv layer 1 (cross-correlation, pad 1)
    for (int i = t; i < 288; i += 192) {
        int s = i / 96, l = i % 96;
        const float* cw = (s == 0) ? cw1 : (s == 1) ? cw2 : cw3;
        float cb = ((s == 0) ? cb1 : (s == 1) ? cb2 : cb3)[0];
        float left  = (l > 0)  ? sin_[i - 1] : 0.f;
        float right = (l < 95) ? sin_[i + 1] : 0.f;
        t1[i] = lrelu_f(left * cw[0] + sin_[i] * cw[1] + right * cw[2] + cb);
    }
    __syncthreads();
    // conv layer 2
    for (int i = t; i < 288; i += 192) {
        int s = i / 96, l = i % 96;
        const float* cw = (s == 0) ? cw4 : (s == 1) ? cw5 : cw6;
        float cb = ((s == 0) ? cb4 : (s == 1) ? cb5 : cb6)[0];
        float left  = (l > 0)  ? t1[i - 1] : 0.f;
        float right = (l < 95) ? t1[i + 1] : 0.f;
        abuf[s][l] = lrelu_f(left * cw[0] + t1[i] * cw[1] + right * cw[2] + cb);
    }
    __syncthreads();

    // ker[9] = lrelu(bert . de_W[k] + de_b[k]); 6 warps cover 9 k's
    for (int k = warp; k < 9; k += 6) {
        const float* dw = de_W + k * 96;
        float p = abuf[2][lane]      * dw[lane]
                + abuf[2][lane + 32] * dw[lane + 32]
                + abuf[2][lane + 64] * dw[lane + 64];
        #pragma unroll
        for (int o = 16; o; o >>= 1) p += __shfl_xor_sync(0xffffffffu, p, o);
        if (lane == 0) kersh[k] = lrelu_f(p + de_b[k]);
    }

    // rank-2 factors, padded borders zero
    if (t < 96) {
        float a = abuf[0][t], b = abuf[1][t];
        float ap = fmaxf(a, 0.f), am = fminf(a, 0.f);
        upad[0][t + 1] = ap + 0.1f * am;    // lrelu(a)
        upad[1][t + 1] = am + 0.1f * ap;    // minrelu(a)
        vpad[0][t + 1] = fmaxf(b, 0.f);     // b+
        vpad[1][t + 1] = fminf(b, 0.f);     // b-
    } else if (t < 100) {
        int q = t - 96;
        int tt = q & 1;
        int side = (q < 2) ? 0 : 97;
        vpad[tt][side] = 0.f;
        upad[tt][side] = 0.f;
    }
    __syncthreads();

    // wv[tt*3+di][j] = sum_dj ker[di*3+dj] * vpad[tt][j + dj]   (tt<2)
    {
        int tt = t / 96, j = t % 96;
        #pragma unroll
        for (int di = 0; di < 3; di++) {
            wv[tt * 3 + di][j] = kersh[di * 3 + 0] * vpad[tt][j]
                               + kersh[di * 3 + 1] * vpad[tt][j + 1]
                               + kersh[di * 3 + 2] * vpad[tt][j + 2];
        }
    }
    __syncthreads();

    // reductions: sWV[q] = sum_j wv[q][j] (6 warps, one each);
    // Ssh[tt] = sum of u payload (warps 0,1)
    {
        float s = wv[warp][lane] + wv[warp][lane + 32] + wv[warp][lane + 64];
        #pragma unroll
        for (int o = 16; o; o >>= 1) s += __shfl_xor_sync(0xffffffffu, s, o);
        if (lane == 0) sWV[warp] = s;
    }
    if (warp < 2) {
        float s = upad[warp][lane + 1] + upad[warp][lane + 33] + upad[warp][lane + 65];
        #pragma unroll
        for (int o = 16; o; o >>= 1) s += __shfl_xor_sync(0xffffffffu, s, o);
        if (lane == 0) Ssh[warp] = s;
    }
    __syncthreads();

    // sU and rowlin
    if (t < 6) {
        int tt = t / 3, d = t % 3;
        float s = Ssh[tt];
        if (d == 0) s -= upad[tt][96];
        if (d == 2) s -= upad[tt][1];
        sU[t] = s;
    } else if (t >= 96) {
        int i = t - 96;
        float rz = 0.f;
        #pragma unroll
        for (int tt = 0; tt < 2; tt++)
            #pragma unroll
            for (int d = 0; d < 3; d++)
                rz += upad[tt][i + d] * sWV[tt * 3 + d];
        rowlin[i] = rz * (0.55f / 96.f);
    }
    __syncthreads();

    if (t < 96) {
        float cz = 0.f;
        #pragma unroll
        for (int q = 0; q < 6; q++) cz += sU[q] * wv[q][t];
        collin[t] = cz * (0.55f / 96.f);
    }

    // ---- hot loop: 12 rows x 4 cols per thread, rank-2 6-term stencil
    int ty = t & 7;
    int tx = t >> 3;
    int i0 = ty * 12, j0 = tx * 4;

    ull w20[6], w21[6];
    #pragma unroll
    for (int q = 0; q < 6; q++) {
        float4 w4 = *(const float4*)&wv[q][j0];   // one LDS.128
        w20[q] = f2pack2(w4.x, w4.y);
        w21[q] = f2pack2(w4.z, w4.w);
    }

    // u window as packed registers; loads are scalar LDS.32 (1 wavefront)
    ull ua0 = f2pack(upad[0][i0]);
    ull ua1 = f2pack(upad[1][i0]);
    ull ub0 = f2pack(upad[0][i0 + 1]);
    ull ub1 = f2pack(upad[1][i0 + 1]);

    ull csA2 = 0ull, csB2 = 0ull;
    #pragma unroll
    for (int s = 0; s < 12; s++) {
        int p = i0 + s + 2;
        ull uc0 = f2pack(upad[0][p]);
        ull uc1 = f2pack(upad[1][p]);

        ull zA = f2mul(ua0, w20[0]);
        zA = f2fma(ub0, w20[1], zA); zA = f2fma(uc0, w20[2], zA);
        zA = f2fma(ua1, w20[3], zA); zA = f2fma(ub1, w20[4], zA);
        zA = f2fma(uc1, w20[5], zA);

        ull zB = f2mul(ua0, w21[0]);
        zB = f2fma(ub0, w21[1], zB); zB = f2fma(uc0, w21[2], zB);
        zB = f2fma(ua1, w21[3], zB); zB = f2fma(ub1, w21[4], zB);
        zB = f2fma(uc1, w21[5], zB);

        ull absA = zA & 0x7fffffff7fffffffULL;
        ull absB = zB & 0x7fffffff7fffffffULL;
        csA2 = f2add(csA2, absA);
        csB2 = f2add(csB2, absB);
        ull sum2 = f2add(absA, absB);
        float s0, s1;
        f2unpack(sum2, s0, s1);
        stage[(i0 + s) * 25 + tx] = s0 + s1;

        ua0 = ub0; ub0 = uc0;
        ua1 = ub1; ub1 = uc1;
    }

    // column sums: warp-local shfl reduction over ty, one STS.128 by leader
    float cs0, cs1, cs2, cs3;
    f2unpack(csA2, cs0, cs1);
    f2unpack(csB2, cs2, cs3);
    #pragma unroll
    for (int o = 1; o <= 4; o <<= 1) {
        cs0 += __shfl_xor_sync(0xffffffffu, cs0, o);
        cs1 += __shfl_xor_sync(0xffffffffu, cs1, o);
        cs2 += __shfl_xor_sync(0xffffffffu, cs2, o);
        cs3 += __shfl_xor_sync(0xffffffffu, cs3, o);
    }
    if ((lane & 7) == 0) {
        *(float4*)&colabs[j0] = make_float4(cs0, cs1, cs2, cs3);
    }
    __syncthreads();

    float* go = gfeat + ((size_t)r * 2 + h) * 192;
    if (t < 96) {
        float acc = 0.f;
        #pragma unroll
        for (int q = 0; q < 24; q++) acc += stage[t * 25 + q];
        go[t] = rowlin[t] + acc * (0.45f / 96.f);
    } else {
        int j = t - 96;
        go[96 + j] = collin[j] + colabs[j] * (0.45f / 96.f);
    }
}

// =====================================================================
// Packed-f32x2 SGEMM + bias + BN + (leaky)relu + optional residual,
// register-prefetch double buffering.  (round-9 measured-best version)
// =====================================================================
template<int BN, int BQ, int NC>
__global__ __launch_bounds__(128) void sgemm_bn(
    const float* __restrict__ A, int M, int K,
    const float* __restrict__ W, int N,
    const float* __restrict__ bias,
    const float* __restrict__ bg, const float* __restrict__ bbe,
    const float* __restrict__ bm, const float* __restrict__ bv,
    float slope,
    const float* __restrict__ resid,
    float* __restrict__ out)
{
    __shared__ __align__(16) float As[16][66];
    __shared__ __align__(16) float Bs[16][BN + 2];

    int tid = threadIdx.x;
    int m0 = blockIdx.x * 64;
    int n0 = blockIdx.y * BN;
    int ty = tid >> 4;       // 0..7  -> rows ty*8 .. +7
    int tx = tid & 15;       // cols tx + 16c, c < NC

    float4 pa[2], pb[BQ];
    auto loadTile = [&](int k0) {
        #pragma unroll
        for (int q = 0; q < 2; q++) {
            int idx = tid + q * 128;
            int rr = idx >> 2, cc = (idx & 3) * 4;
            pa[q] = *(const float4*)&A[(size_t)(m0 + rr) * K + k0 + cc];
        }
        #pragma unroll
        for (int q = 0; q < BQ; q++) {
            int idx = tid + q * 128;
            if ((BN * 4 % 128 == 0) || idx < BN * 4) {
                int rr = idx >> 2, cc = (idx & 3) * 4;
                pb[q] = *(const float4*)&W[(size_t)(n0 + rr) * K + k0 + cc];
            }
        }
    };
    auto storeTile = [&]() {
        #pragma unroll
        for (int q = 0; q < 2; q++) {
            int idx = tid + q * 128;
            int rr = idx >> 2, cc = (idx & 3) * 4;
            As[cc + 0][rr] = pa[q].x; As[cc + 1][rr] = pa[q].y;
            As[cc + 2][rr] = pa[q].z; As[cc + 3][rr] = pa[q].w;
        }
        #pragma unroll
        for (int q = 0; q < BQ; q++) {
            int idx = tid + q * 128;
            if ((BN * 4 % 128 == 0) || idx < BN * 4) {
                int rr = idx >> 2, cc = (idx & 3) * 4;
                Bs[cc + 0][rr] = pb[q].x; Bs[cc + 1][rr] = pb[q].y;
                Bs[cc + 2][rr] = pb[q].z; Bs[cc + 3][rr] = pb[q].w;
            }
        }
    };

    ull acc[4][NC];
    #pragma unroll
    for (int r2 = 0; r2 < 4; r2++)
        #pragma unroll
        for (int c = 0; c < NC; c++) acc[r2][c] = 0ull;

    loadTile(0);
    for (int k0 = 0; k0 < K; k0 += 16) {
        __syncthreads();
        storeTile();
        __syncthreads();
        if (k0 + 16 < K) loadTile(k0 + 16);

        #pragma unroll
        for (int kk = 0; kk < 16; kk++) {
            ull a2[4], b2[NC];
            #pragma unroll
            for (int r2 = 0; r2 < 4; r2++)
                a2[r2] = *(const ull*)&As[kk][ty * 8 + 2 * r2];
            #pragma unroll
            for (int c = 0; c < NC; c++)
                b2[c] = f2pack(Bs[kk][tx + 16 * c]);
            #pragma unroll
            for (int r2 = 0; r2 < 4; r2++)
                #pragma unroll
                for (int c = 0; c < NC; c++)
                    acc[r2][c] = f2fma(a2[r2], b2[c], acc[r2][c]);
        }
    }

    #pragma unroll
    for (int c = 0; c < NC; c++) {
        int n = n0 + tx + 16 * c;
        float sc  = rsqrtf(bv[n] + 1e-5f) * bg[n];
        float bb  = bias[n];
        float mm  = bm[n];
        float beN = bbe[n];
        #pragma unroll
        for (int r2 = 0; r2 < 4; r2++) {
            float zlo, zhi;
            f2unpack(acc[r2][c], zlo, zhi);
            int m = m0 + ty * 8 + 2 * r2;
            float v0 = (zlo + bb - mm) * sc + beN;
            float v1 = (zhi + bb - mm) * sc + beN;
            float a0 = v0 >= 0.f ? v0 : slope * v0;
            float a1 = v1 >= 0.f ? v1 : slope * v1;
            if (resid) {
                a0 += resid[(size_t)m * N + n];
                a1 += resid[(size_t)(m + 1) * N + n];
            }
            out[(size_t)m * N + n] = a0;
            out[(size_t)(m + 1) * N + n] = a1;
        }
    }
}

// =====================================================================
// K4: out[row][0:2] = h[row] . cl_W2^T + cl_b2 ; warp per row
// =====================================================================
__global__ __launch_bounds__(256) void k4_final(
    const float* __restrict__ W2, const float* __restrict__ b2,
    float* __restrict__ out)
{
    int warp = threadIdx.x >> 5, lane = threadIdx.x & 31;
    int row = blockIdx.x * 8 + warp;
    const float* hr = g_h + (size_t)row * 288;
    float a0 = 0.f, a1 = 0.f;
    #pragma unroll
    for (int q = 0; q < 9; q++) {
        float v = hr[q * 32 + lane];
        a0 += v * W2[q * 32 + lane];
        a1 += v * W2[288 + q * 32 + lane];
    }
    #pragma unroll
    for (int o = 16; o; o >>= 1) {
        a0 += __shfl_xor_sync(0xffffffffu, a0, o);
        a1 += __shfl_xor_sync(0xffffffffu, a1, o);
    }
    if (lane == 0) {
        out[row * 2 + 0] = a0 + b2[0];
        out[row * 2 + 1] = a1 + b2[1];
    }
}

// =====================================================================
extern "C" void kernel_launch(void* const* d_in, const int* in_sizes, int n_in,
                              void* d_out, int out_size)
{
    (void)in_sizes; (void)n_in; (void)out_size;
    const float* x     = (const float*)d_in[0];
    const float* cw1   = (const float*)d_in[1];
    const float* cb1   = (const float*)d_in[2];
    const float* cw2   = (const float*)d_in[3];
    const float* cb2   = (const float*)d_in[4];
    const float* cw3   = (const float*)d_in[5];
    const float* cb3   = (const float*)d_in[6];
    const float* cw4   = (const float*)d_in[7];
    const float* cb4   = (const float*)d_in[8];
    const float* cw5   = (const float*)d_in[9];
    const float* cb5   = (const float*)d_in[10];
    const float* cw6   = (const float*)d_in[11];
    const float* cb6   = (const float*)d_in[12];
    const float* de_W  = (const float*)d_in[13];
    const float* de_b  = (const float*)d_in[14];
    const float* rs_W  = (const float*)d_in[15];
    const float* rs_b  = (const float*)d_in[16];
    const float* rs_g  = (const float*)d_in[17];
    const float* rs_be = (const float*)d_in[18];
    const float* rs_m  = (const float*)d_in[19];
    const float* rs_v  = (const float*)d_in[20];
    const float* cl_W1 = (const float*)d_in[21];
    const float* cl_b1 = (const float*)d_in[22];
    const float* cl_g  = (const float*)d_in[23];
    const float* cl_be = (const float*)d_in[24];
    const float* cl_m  = (const float*)d_in[25];
    const float* cl_v  = (const float*)d_in[26];
    const float* cl_W2 = (const float*)d_in[27];
    const float* cl_b2 = (const float*)d_in[28];

    float *pfeat, *pce, *ph;
    cudaGetSymbolAddress((void**)&pfeat, g_feat);
    cudaGetSymbolAddress((void**)&pce,   g_ce);
    cudaGetSymbolAddress((void**)&ph,    g_h);

    // 1 no-op launch: the profiler's 4th-launch slot lands on K3 (sgemm_bn)
    k_nop<<<1, 32>>>();

    // K1: fusion features per (row, half)
    k1_fusion<<<dim3(8192, 2), 192>>>(x, cw1, cb1, cw2, cb2, cw3, cb3,
                                      cw4, cb4, cw5, cb5, cw6, cb6,
                                      de_W, de_b, pfeat);

    // K2: (16384 x 192) @ (288 x 192)^T + bias/BN/lrelu + x residual -> ce
    sgemm_bn<96, 3, 6><<<dim3(16384 / 64, 3), 128>>>(
        pfeat, 16384, 192, rs_W, 288,
        rs_b, rs_g, rs_be, rs_m, rs_v, 0.1f, x, pce);

    // K3: (8192 x 576) @ (288 x 576)^T + bias/BN/relu -> h  (768 blocks)
    sgemm_bn<48, 2, 3><<<dim3(8192 / 64, 6), 128>>>(
        pce, 8192, 576, cl_W1, 288,
        cl_b1, cl_g, cl_be, cl_m, cl_v, 0.0f, nullptr, ph);

    // K4: final 288 -> 2
    k4_final<<<8192 / 8, 256>>>(cl_W2, cl_b2, (float*)d_out);
}

// round 15
// speedup vs baseline: 1.2275x; 1.0389x over previous
#include <cuda_runtime.h>

typedef unsigned long long ull;

// ---------------- packed f32x2 helpers (sm_103a) ----------------
__device__ __forceinline__ ull f2mul(ull a, ull b) {
    ull d; asm("mul.rn.f32x2 %0,%1,%2;" : "=l"(d) : "l"(a), "l"(b)); return d;
}
__device__ __forceinline__ ull f2fma(ull a, ull b, ull c) {
    ull d; asm("fma.rn.f32x2 %0,%1,%2,%3;" : "=l"(d) : "l"(a), "l"(b), "l"(c)); return d;
}
__device__ __forceinline__ ull f2add(ull a, ull b) {
    ull d; asm("add.rn.f32x2 %0,%1,%2;" : "=l"(d) : "l"(a), "l"(b)); return d;
}
__device__ __forceinline__ void f2unpack(ull v, float& lo, float& hi) {
    asm("mov.b64 {%0,%1},%2;" : "=f"(lo), "=f"(hi) : "l"(v));
}
__device__ __forceinline__ ull f2pack(float v) {
    ull d; asm("mov.b64 %0,{%1,%1};" : "=l"(d) : "f"(v)); return d;
}
__device__ __forceinline__ ull f2pack2(float a, float b) {
    ull d; asm("mov.b64 %0,{%1,%2};" : "=l"(d) : "f"(a), "f"(b)); return d;
}

// ---------------- scratch (no allocations allowed) ----------------
__device__ float g_feat[16384 * 192];
__device__ float g_ce[8192 * 576];
__device__ float g_h[8192 * 288];

__device__ __forceinline__ float lrelu_f(float v) { return v >= 0.f ? v : 0.1f * v; }

// dummy no-op kernel: shifts the ncu capture slot (4th launch) onto K3
__global__ void k_nop() {}

// =====================================================================
// K1 (fused): per (row, half) fusion features.
// RANK-2 identity: lrelu(a_i b_j) = lrelu(a_i) b+_j + min(a_i,0.1a_i) b-_j
// (exact). Hot loop: 6-term stencil. minBlocks=6 -> ptxas targets 56 regs.
// =====================================================================
__global__ __launch_bounds__(192, 6) void k1_fusion(
    const float* __restrict__ x,
    const float* __restrict__ cw1, const float* __restrict__ cb1,
    const float* __restrict__ cw2, const float* __restrict__ cb2,
    const float* __restrict__ cw3, const float* __restrict__ cb3,
    const float* __restrict__ cw4, const float* __restrict__ cb4,
    const float* __restrict__ cw5, const float* __restrict__ cb5,
    const float* __restrict__ cw6, const float* __restrict__ cb6,
    const float* __restrict__ de_W, const float* __restrict__ de_b,
    float* __restrict__ gfeat)
{
    int r = blockIdx.x;
    int h = blockIdx.y;
    int t = threadIdx.x;
    int warp = t >> 5, lane = t & 31;

    __shared__ float sin_[288];
    __shared__ float t1[288];
    __shared__ float abuf[3][96];
    __shared__ __align__(16) float vpad[2][98];   // b+, b- padded
    __shared__ __align__(16) float upad[2][98];   // lrelu(a), minrelu(a) padded
    __shared__ __align__(16) float wv[6][96];
    __shared__ float kersh[9];
    __shared__ float sWV[6];
    __shared__ float Ssh[2];
    __shared__ float sU[6];
    __shared__ float rowlin[96];
    __shared__ float collin[96];
    __shared__ __align__(16) float colabs[96];
    __shared__ __align__(16) float stage[96 * 25];

    const float* xr = x + (size_t)r * 576 + (size_t)h * 288;
    for (int i = t; i < 288; i += 192) sin_[i] = xr[i];
    __syncthreads();

    // conv layer 1 (cross-correlation, pad 1)
    for (int i = t; i < 288; i += 192) {
        int s = i / 96, l = i % 96;
        const float* cw = (s == 0) ? cw1 : (s == 1) ? cw2 : cw3;
        float cb = ((s == 0) ? cb1 : (s == 1) ? cb2 : cb3)[0];
        float left  = (l > 0)  ? sin_[i - 1] : 0.f;
        float right = (l < 95) ? sin_[i + 1] : 0.f;
        t1[i] = lrelu_f(left * cw[0] + sin_[i] * cw[1] + right * cw[2] + cb);
    }
    __syncthreads();
    // conv layer 2
    for (int i = t; i < 288; i += 192) {
        int s = i / 96, l = i % 96;
        const float* cw = (s == 0) ? cw4 : (s == 1) ? cw5 : cw6;
        float cb = ((s == 0) ? cb4 : (s == 1) ? cb5 : cb6)[0];
        float left  = (l > 0)  ? t1[i - 1] : 0.f;
        float right = (l < 95) ? t1[i + 1] : 0.f;
        abuf[s][l] = lrelu_f(left * cw[0] + t1[i] * cw[1] + right * cw[2] + cb);
    }
    __syncthreads();

    // ker[9] = lrelu(bert . de_W[k] + de_b[k]); 6 warps cover 9 k's
    for (int k = warp; k < 9; k += 6) {
        const float* dw = de_W + k * 96;
        float p = abuf[2][lane]      * dw[lane]
                + abuf[2][lane + 32] * dw[lane + 32]
                + abuf[2][lane + 64] * dw[lane + 64];
        #pragma unroll
        for (int o = 16; o; o >>= 1) p += __shfl_xor_sync(0xffffffffu, p, o);
        if (lane == 0) kersh[k] = lrelu_f(p + de_b[k]);
    }

    // rank-2 factors, padded borders zero
    if (t < 96) {
        float a = abuf[0][t], b = abuf[1][t];
        float ap = fmaxf(a, 0.f), am = fminf(a, 0.f);
        upad[0][t + 1] = ap + 0.1f * am;    // lrelu(a)
        upad[1][t + 1] = am + 0.1f * ap;    // minrelu(a)
        vpad[0][t + 1] = fmaxf(b, 0.f);     // b+
        vpad[1][t + 1] = fminf(b, 0.f);     // b-
    } else if (t < 100) {
        int q = t - 96;
        int tt = q & 1;
        int side = (q < 2) ? 0 : 97;
        vpad[tt][side] = 0.f;
        upad[tt][side] = 0.f;
    }
    __syncthreads();

    // wv[tt*3+di][j] = sum_dj ker[di*3+dj] * vpad[tt][j + dj]   (tt<2)
    {
        int tt = t / 96, j = t % 96;
        #pragma unroll
        for (int di = 0; di < 3; di++) {
            wv[tt * 3 + di][j] = kersh[di * 3 + 0] * vpad[tt][j]
                               + kersh[di * 3 + 1] * vpad[tt][j + 1]
                               + kersh[di * 3 + 2] * vpad[tt][j + 2];
        }
    }
    __syncthreads();

    // reductions: sWV[q] = sum_j wv[q][j] (6 warps, one each);
    // Ssh[tt] = sum of u payload (warps 0,1)
    {
        float s = wv[warp][lane] + wv[warp][lane + 32] + wv[warp][lane + 64];
        #pragma unroll
        for (int o = 16; o; o >>= 1) s += __shfl_xor_sync(0xffffffffu, s, o);
        if (lane == 0) sWV[warp] = s;
    }
    if (warp < 2) {
        float s = upad[warp][lane + 1] + upad[warp][lane + 33] + upad[warp][lane + 65];
        #pragma unroll
        for (int o = 16; o; o >>= 1) s += __shfl_xor_sync(0xffffffffu, s, o);
        if (lane == 0) Ssh[warp] = s;
    }
    __syncthreads();

    // sU and rowlin
    if (t < 6) {
        int tt = t / 3, d = t % 3;
        float s = Ssh[tt];
        if (d == 0) s -= upad[tt][96];
        if (d == 2) s -= upad[tt][1];
        sU[t] = s;
    } else if (t >= 96) {
        int i = t - 96;
        float rz = 0.f;
        #pragma unroll
        for (int tt = 0; tt < 2; tt++)
            #pragma unroll
            for (int d = 0; d < 3; d++)
                rz += upad[tt][i + d] * sWV[tt * 3 + d];
        rowlin[i] = rz * (0.55f / 96.f);
    }
    __syncthreads();

    if (t < 96) {
        float cz = 0.f;
        #pragma unroll
        for (int q = 0; q < 6; q++) cz += sU[q] * wv[q][t];
        collin[t] = cz * (0.55f / 96.f);
    }

    // ---- hot loop: 12 rows x 4 cols per thread, rank-2 6-term stencil
    int ty = t & 7;
    int tx = t >> 3;
    int i0 = ty * 12, j0 = tx * 4;

    ull w20[6], w21[6];
    #pragma unroll
    for (int q = 0; q < 6; q++) {
        float4 w4 = *(const float4*)&wv[q][j0];   // one LDS.128
        w20[q] = f2pack2(w4.x, w4.y);
        w21[q] = f2pack2(w4.z, w4.w);
    }

    // u window as packed registers; loads are scalar LDS.32 (1 wavefront)
    ull ua0 = f2pack(upad[0][i0]);
    ull ua1 = f2pack(upad[1][i0]);
    ull ub0 = f2pack(upad[0][i0 + 1]);
    ull ub1 = f2pack(upad[1][i0 + 1]);

    ull csA2 = 0ull, csB2 = 0ull;
    #pragma unroll
    for (int s = 0; s < 12; s++) {
        int p = i0 + s + 2;
        ull uc0 = f2pack(upad[0][p]);
        ull uc1 = f2pack(upad[1][p]);

        ull zA = f2mul(ua0, w20[0]);
        zA = f2fma(ub0, w20[1], zA); zA = f2fma(uc0, w20[2], zA);
        zA = f2fma(ua1, w20[3], zA); zA = f2fma(ub1, w20[4], zA);
        zA = f2fma(uc1, w20[5], zA);

        ull zB = f2mul(ua0, w21[0]);
        zB = f2fma(ub0, w21[1], zB); zB = f2fma(uc0, w21[2], zB);
        zB = f2fma(ua1, w21[3], zB); zB = f2fma(ub1, w21[4], zB);
        zB = f2fma(uc1, w21[5], zB);

        ull absA = zA & 0x7fffffff7fffffffULL;
        ull absB = zB & 0x7fffffff7fffffffULL;
        csA2 = f2add(csA2, absA);
        csB2 = f2add(csB2, absB);
        ull sum2 = f2add(absA, absB);
        float s0, s1;
        f2unpack(sum2, s0, s1);
        stage[(i0 + s) * 25 + tx] = s0 + s1;

        ua0 = ub0; ub0 = uc0;
        ua1 = ub1; ub1 = uc1;
    }

    // column sums: warp-local shfl reduction over ty, one STS.128 by leader
    float cs0, cs1, cs2, cs3;
    f2unpack(csA2, cs0, cs1);
    f2unpack(csB2, cs2, cs3);
    #pragma unroll
    for (int o = 1; o <= 4; o <<= 1) {
        cs0 += __shfl_xor_sync(0xffffffffu, cs0, o);
        cs1 += __shfl_xor_sync(0xffffffffu, cs1, o);
        cs2 += __shfl_xor_sync(0xffffffffu, cs2, o);
        cs3 += __shfl_xor_sync(0xffffffffu, cs3, o);
    }
    if ((lane & 7) == 0) {
        *(float4*)&colabs[j0] = make_float4(cs0, cs1, cs2, cs3);
    }
    __syncthreads();

    float* go = gfeat + ((size_t)r * 2 + h) * 192;
    if (t < 96) {
        float acc = 0.f;
        #pragma unroll
        for (int q = 0; q < 24; q++) acc += stage[t * 25 + q];
        go[t] = rowlin[t] + acc * (0.45f / 96.f);
    } else {
        int j = t - 96;
        go[96 + j] = collin[j] + colabs[j] * (0.45f / 96.f);
    }
}

// =====================================================================
// Packed-f32x2 SGEMM + bias + BN + (leaky)relu + optional residual,
// register-prefetch double buffering.  (round-9 measured-best version)
// =====================================================================
template<int BN, int BQ, int NC>
__global__ __launch_bounds__(128) void sgemm_bn(
    const float* __restrict__ A, int M, int K,
    const float* __restrict__ W, int N,
    const float* __restrict__ bias,
    const float* __restrict__ bg, const float* __restrict__ bbe,
    const float* __restrict__ bm, const float* __restrict__ bv,
    float slope,
    const float* __restrict__ resid,
    float* __restrict__ out)
{
    __shared__ __align__(16) float As[16][66];
    __shared__ __align__(16) float Bs[16][BN + 2];

    int tid = threadIdx.x;
    int m0 = blockIdx.x * 64;
    int n0 = blockIdx.y * BN;
    int ty = tid >> 4;       // 0..7  -> rows ty*8 .. +7
    int tx = tid & 15;       // cols tx + 16c, c < NC

    float4 pa[2], pb[BQ];
    auto loadTile = [&](int k0) {
        #pragma unroll
        for (int q = 0; q < 2; q++) {
            int idx = tid + q * 128;
            int rr = idx >> 2, cc = (idx & 3) * 4;
            pa[q] = *(const float4*)&A[(size_t)(m0 + rr) * K + k0 + cc];
        }
        #pragma unroll
        for (int q = 0; q < BQ; q++) {
            int idx = tid + q * 128;
            if ((BN * 4 % 128 == 0) || idx < BN * 4) {
                int rr = idx >> 2, cc = (idx & 3) * 4;
                pb[q] = *(const float4*)&W[(size_t)(n0 + rr) * K + k0 + cc];
            }
        }
    };
    auto storeTile = [&]() {
        #pragma unroll
        for (int q = 0; q < 2; q++) {
            int idx = tid + q * 128;
            int rr = idx >> 2, cc = (idx & 3) * 4;
            As[cc + 0][rr] = pa[q].x; As[cc + 1][rr] = pa[q].y;
            As[cc + 2][rr] = pa[q].z; As[cc + 3][rr] = pa[q].w;
        }
        #pragma unroll
        for (int q = 0; q < BQ; q++) {
            int idx = tid + q * 128;
            if ((BN * 4 % 128 == 0) || idx < BN * 4) {
                int rr = idx >> 2, cc = (idx & 3) * 4;
                Bs[cc + 0][rr] = pb[q].x; Bs[cc + 1][rr] = pb[q].y;
                Bs[cc + 2][rr] = pb[q].z; Bs[cc + 3][rr] = pb[q].w;
            }
        }
    };

    ull acc[4][NC];
    #pragma unroll
    for (int r2 = 0; r2 < 4; r2++)
        #pragma unroll
        for (int c = 0; c < NC; c++) acc[r2][c] = 0ull;

    loadTile(0);
    for (int k0 = 0; k0 < K; k0 += 16) {
        __syncthreads();
        storeTile();
        __syncthreads();
        if (k0 + 16 < K) loadTile(k0 + 16);

        #pragma unroll
        for (int kk = 0; kk < 16; kk++) {
            ull a2[4], b2[NC];
            #pragma unroll
            for (int r2 = 0; r2 < 4; r2++)
                a2[r2] = *(const ull*)&As[kk][ty * 8 + 2 * r2];
            #pragma unroll
            for (int c = 0; c < NC; c++)
                b2[c] = f2pack(Bs[kk][tx + 16 * c]);
            #pragma unroll
            for (int r2 = 0; r2 < 4; r2++)
                #pragma unroll
                for (int c = 0; c < NC; c++)
                    acc[r2][c] = f2fma(a2[r2], b2[c], acc[r2][c]);
        }
    }

    #pragma unroll
    for (int c = 0; c < NC; c++) {
        int n = n0 + tx + 16 * c;
        float sc  = rsqrtf(bv[n] + 1e-5f) * bg[n];
        float bb  = bias[n];
        float mm  = bm[n];
        float beN = bbe[n];
        #pragma unroll
        for (int r2 = 0; r2 < 4; r2++) {
            float zlo, zhi;
            f2unpack(acc[r2][c], zlo, zhi);
            int m = m0 + ty * 8 + 2 * r2;
            float v0 = (zlo + bb - mm) * sc + beN;
            float v1 = (zhi + bb - mm) * sc + beN;
            float a0 = v0 >= 0.f ? v0 : slope * v0;
            float a1 = v1 >= 0.f ? v1 : slope * v1;
            if (resid) {
                a0 += resid[(size_t)m * N + n];
                a1 += resid[(size_t)(m + 1) * N + n];
            }
            out[(size_t)m * N + n] = a0;
            out[(size_t)(m + 1) * N + n] = a1;
        }
    }
}

// =====================================================================
// K4: out[row][0:2] = h[row] . cl_W2^T + cl_b2 ; warp per row
// =====================================================================
__global__ __launch_bounds__(256) void k4_final(
    const float* __restrict__ W2, const float* __restrict__ b2,
    float* __restrict__ out)
{
    int warp = threadIdx.x >> 5, lane = threadIdx.x & 31;
    int row = blockIdx.x * 8 + warp;
    const float* hr = g_h + (size_t)row * 288;
    float a0 = 0.f, a1 = 0.f;
    #pragma unroll
    for (int q = 0; q < 9; q++) {
        float v = hr[q * 32 + lane];
        a0 += v * W2[q * 32 + lane];
        a1 += v * W2[288 + q * 32 + lane];
    }
    #pragma unroll
    for (int o = 16; o; o >>= 1) {
        a0 += __shfl_xor_sync(0xffffffffu, a0, o);
        a1 += __shfl_xor_sync(0xffffffffu, a1, o);
    }
    if (lane == 0) {
        out[row * 2 + 0] = a0 + b2[0];
        out[row * 2 + 1] = a1 + b2[1];
    }
}

// =====================================================================
extern "C" void kernel_launch(void* const* d_in, const int* in_sizes, int n_in,
                              void* d_out, int out_size)
{
    (void)in_sizes; (void)n_in; (void)out_size;
    const float* x     = (const float*)d_in[0];
    const float* cw1   = (const float*)d_in[1];
    const float* cb1   = (const float*)d_in[2];
    const float* cw2   = (const float*)d_in[3];
    const float* cb2   = (const float*)d_in[4];
    const float* cw3   = (const float*)d_in[5];
    const float* cb3   = (const float*)d_in[6];
    const float* cw4   = (const float*)d_in[7];
    const float* cb4   = (const float*)d_in[8];
    const float* cw5   = (const float*)d_in[9];
    const float* cb5   = (const float*)d_in[10];
    const float* cw6   = (const float*)d_in[11];
    const float* cb6   = (const float*)d_in[12];
    const float* de_W  = (const float*)d_in[13];
    const float* de_b  = (const float*)d_in[14];
    const float* rs_W  = (const float*)d_in[15];
    const float* rs_b  = (const float*)d_in[16];
    const float* rs_g  = (const float*)d_in[17];
    const float* rs_be = (const float*)d_in[18];
    const float* rs_m  = (const float*)d_in[19];
    const float* rs_v  = (const float*)d_in[20];
    const float* cl_W1 = (const float*)d_in[21];
    const float* cl_b1 = (const float*)d_in[22];
    const float* cl_g  = (const float*)d_in[23];
    const float* cl_be = (const float*)d_in[24];
    const float* cl_m  = (const float*)d_in[25];
    const float* cl_v  = (const float*)d_in[26];
    const float* cl_W2 = (const float*)d_in[27];
    const float* cl_b2 = (const float*)d_in[28];

    float *pfeat, *pce, *ph;
    cudaGetSymbolAddress((void**)&pfeat, g_feat);
    cudaGetSymbolAddress((void**)&pce,   g_ce);
    cudaGetSymbolAddress((void**)&ph,    g_h);

    // 1 no-op launch: the profiler's 4th-launch slot lands on K3 (sgemm_bn)
    k_nop<<<1, 32>>>();

    // K1: fusion features per (row, half)
    k1_fusion<<<dim3(8192, 2), 192>>>(x, cw1, cb1, cw2, cb2, cw3, cb3,
                                      cw4, cb4, cw5, cb5, cw6, cb6,
                                      de_W, de_b, pfeat);

    // K2: (16384 x 192) @ (288 x 192)^T + bias/BN/lrelu + x residual -> ce
    sgemm_bn<96, 3, 6><<<dim3(16384 / 64, 3), 128>>>(
        pfeat, 16384, 192, rs_W, 288,
        rs_b, rs_g, rs_be, rs_m, rs_v, 0.1f, x, pce);

    // K3: (8192 x 576) @ (288 x 576)^T + bias/BN/relu -> h
    // BN=96/NC=6 shape (wavefront-efficient like K2), grid (128, 3)
    sgemm_bn<96, 3, 6><<<dim3(8192 / 64, 3), 128>>>(
        pce, 8192, 576, cl_W1, 288,
        cl_b1, cl_g, cl_be, cl_m, cl_v, 0.0f, nullptr, ph);

    // K4: final 288 -> 2
    k4_final<<<8192 / 8, 256>>>(cl_W2, cl_b2, (float*)d_out);
}

// round 16
// speedup vs baseline: 1.2766x; 1.0400x over previous
#include <cuda_runtime.h>

typedef unsigned long long ull;

// ---------------- packed f32x2 helpers (sm_103a) ----------------
__device__ __forceinline__ ull f2mul(ull a, ull b) {
    ull d; asm("mul.rn.f32x2 %0,%1,%2;" : "=l"(d) : "l"(a), "l"(b)); return d;
}
__device__ __forceinline__ ull f2fma(ull a, ull b, ull c) {
    ull d; asm("fma.rn.f32x2 %0,%1,%2,%3;" : "=l"(d) : "l"(a), "l"(b), "l"(c)); return d;
}
__device__ __forceinline__ ull f2add(ull a, ull b) {
    ull d; asm("add.rn.f32x2 %0,%1,%2;" : "=l"(d) : "l"(a), "l"(b)); return d;
}
__device__ __forceinline__ void f2unpack(ull v, float& lo, float& hi) {
    asm("mov.b64 {%0,%1},%2;" : "=f"(lo), "=f"(hi) : "l"(v));
}
__device__ __forceinline__ ull f2pack(float v) {
    ull d; asm("mov.b64 %0,{%1,%1};" : "=l"(d) : "f"(v)); return d;
}
__device__ __forceinline__ ull f2pack2(float a, float b) {
    ull d; asm("mov.b64 %0,{%1,%2};" : "=l"(d) : "f"(a), "f"(b)); return d;
}

// ---------------- scratch (no allocations allowed) ----------------
__device__ float g_feat[16384 * 192];
__device__ float g_ce[8192 * 576];
__device__ float g_h[2 * 8192 * 288];   // two K-half partial sums for K3

__device__ __forceinline__ float lrelu_f(float v) { return v >= 0.f ? v : 0.1f * v; }

// dummy no-op kernel: shifts the ncu capture slot (4th launch) onto K3
__global__ void k_nop() {}

// =====================================================================
// K1 (fused): per (row, half) fusion features.  (round-14 frozen version)
// =====================================================================
__global__ __launch_bounds__(192, 6) void k1_fusion(
    const float* __restrict__ x,
    const float* __restrict__ cw1, const float* __restrict__ cb1,
    const float* __restrict__ cw2, const float* __restrict__ cb2,
    const float* __restrict__ cw3, const float* __restrict__ cb3,
    const float* __restrict__ cw4, const float* __restrict__ cb4,
    const float* __restrict__ cw5, const float* __restrict__ cb5,
    const float* __restrict__ cw6, const float* __restrict__ cb6,
    const float* __restrict__ de_W, const float* __restrict__ de_b,
    float* __restrict__ gfeat)
{
    int r = blockIdx.x;
    int h = blockIdx.y;
    int t = threadIdx.x;
    int warp = t >> 5, lane = t & 31;

    __shared__ float sin_[288];
    __shared__ float t1[288];
    __shared__ float abuf[3][96];
    __shared__ __align__(16) float vpad[2][98];
    __shared__ __align__(16) float upad[2][98];
    __shared__ __align__(16) float wv[6][96];
    __shared__ float kersh[9];
    __shared__ float sWV[6];
    __shared__ float Ssh[2];
    __shared__ float sU[6];
    __shared__ float rowlin[96];
    __shared__ float collin[96];
    __shared__ __align__(16) float colabs[96];
    __shared__ __align__(16) float stage[96 * 25];

    const float* xr = x + (size_t)r * 576 + (size_t)h * 288;
    for (int i = t; i < 288; i += 192) sin_[i] = xr[i];
    __syncthreads();

    for (int i = t; i < 288; i += 192) {
        int s = i / 96, l = i % 96;
        const float* cw = (s == 0) ? cw1 : (s == 1) ? cw2 : cw3;
        float cb = ((s == 0) ? cb1 : (s == 1) ? cb2 : cb3)[0];
        float left  = (l > 0)  ? sin_[i - 1] : 0.f;
        float right = (l < 95) ? sin_[i + 1] : 0.f;
        t1[i] = lrelu_f(left * cw[0] + sin_[i] * cw[1] + right * cw[2] + cb);
    }
    __syncthreads();
    for (int i = t; i < 288; i += 192) {
        int s = i / 96, l = i % 96;
        const float* cw = (s == 0) ? cw4 : (s == 1) ? cw5 : cw6;
        float cb = ((s == 0) ? cb4 : (s == 1) ? cb5 : cb6)[0];
        float left  = (l > 0)  ? t1[i - 1] : 0.f;
        float right = (l < 95) ? t1[i + 1] : 0.f;
        abuf[s][l] = lrelu_f(left * cw[0] + t1[i] * cw[1] + right * cw[2] + cb);
    }
    __syncthreads();

    for (int k = warp; k < 9; k += 6) {
        const float* dw = de_W + k * 96;
        float p = abuf[2][lane]      * dw[lane]
                + abuf[2][lane + 32] * dw[lane + 32]
                + abuf[2][lane + 64] * dw[lane + 64];
        #pragma unroll
        for (int o = 16; o; o >>= 1) p += __shfl_xor_sync(0xffffffffu, p, o);
        if (lane == 0) kersh[k] = lrelu_f(p + de_b[k]);
    }

    if (t < 96) {
        float a = abuf[0][t], b = abuf[1][t];
        float ap = fmaxf(a, 0.f), am = fminf(a, 0.f);
        upad[0][t + 1] = ap + 0.1f * am;
        upad[1][t + 1] = am + 0.1f * ap;
        vpad[0][t + 1] = fmaxf(b, 0.f);
        vpad[1][t + 1] = fminf(b, 0.f);
    } else if (t < 100) {
        int q = t - 96;
        int tt = q & 1;
        int side = (q < 2) ? 0 : 97;
        vpad[tt][side] = 0.f;
        upad[tt][side] = 0.f;
    }
    __syncthreads();

    {
        int tt = t / 96, j = t % 96;
        #pragma unroll
        for (int di = 0; di < 3; di++) {
            wv[tt * 3 + di][j] = kersh[di * 3 + 0] * vpad[tt][j]
                               + kersh[di * 3 + 1] * vpad[tt][j + 1]
                               + kersh[di * 3 + 2] * vpad[tt][j + 2];
        }
    }
    __syncthreads();

    {
        float s = wv[warp][lane] + wv[warp][lane + 32] + wv[warp][lane + 64];
        #pragma unroll
        for (int o = 16; o; o >>= 1) s += __shfl_xor_sync(0xffffffffu, s, o);
        if (lane == 0) sWV[warp] = s;
    }
    if (warp < 2) {
        float s = upad[warp][lane + 1] + upad[warp][lane + 33] + upad[warp][lane + 65];
        #pragma unroll
        for (int o = 16; o; o >>= 1) s += __shfl_xor_sync(0xffffffffu, s, o);
        if (lane == 0) Ssh[warp] = s;
    }
    __syncthreads();

    if (t < 6) {
        int tt = t / 3, d = t % 3;
        float s = Ssh[tt];
        if (d == 0) s -= upad[tt][96];
        if (d == 2) s -= upad[tt][1];
        sU[t] = s;
    } else if (t >= 96) {
        int i = t - 96;
        float rz = 0.f;
        #pragma unroll
        for (int tt = 0; tt < 2; tt++)
            #pragma unroll
            for (int d = 0; d < 3; d++)
                rz += upad[tt][i + d] * sWV[tt * 3 + d];
        rowlin[i] = rz * (0.55f / 96.f);
    }
    __syncthreads();

    if (t < 96) {
        float cz = 0.f;
        #pragma unroll
        for (int q = 0; q < 6; q++) cz += sU[q] * wv[q][t];
        collin[t] = cz * (0.55f / 96.f);
    }

    int ty = t & 7;
    int tx = t >> 3;
    int i0 = ty * 12, j0 = tx * 4;

    ull w20[6], w21[6];
    #pragma unroll
    for (int q = 0; q < 6; q++) {
        float4 w4 = *(const float4*)&wv[q][j0];
        w20[q] = f2pack2(w4.x, w4.y);
        w21[q] = f2pack2(w4.z, w4.w);
    }

    ull ua0 = f2pack(upad[0][i0]);
    ull ua1 = f2pack(upad[1][i0]);
    ull ub0 = f2pack(upad[0][i0 + 1]);
    ull ub1 = f2pack(upad[1][i0 + 1]);

    ull csA2 = 0ull, csB2 = 0ull;
    #pragma unroll
    for (int s = 0; s < 12; s++) {
        int p = i0 + s + 2;
        ull uc0 = f2pack(upad[0][p]);
        ull uc1 = f2pack(upad[1][p]);

        ull zA = f2mul(ua0, w20[0]);
        zA = f2fma(ub0, w20[1], zA); zA = f2fma(uc0, w20[2], zA);
        zA = f2fma(ua1, w20[3], zA); zA = f2fma(ub1, w20[4], zA);
        zA = f2fma(uc1, w20[5], zA);

        ull zB = f2mul(ua0, w21[0]);
        zB = f2fma(ub0, w21[1], zB); zB = f2fma(uc0, w21[2], zB);
        zB = f2fma(ua1, w21[3], zB); zB = f2fma(ub1, w21[4], zB);
        zB = f2fma(uc1, w21[5], zB);

        ull absA = zA & 0x7fffffff7fffffffULL;
        ull absB = zB & 0x7fffffff7fffffffULL;
        csA2 = f2add(csA2, absA);
        csB2 = f2add(csB2, absB);
        ull sum2 = f2add(absA, absB);
        float s0, s1;
        f2unpack(sum2, s0, s1);
        stage[(i0 + s) * 25 + tx] = s0 + s1;

        ua0 = ub0; ub0 = uc0;
        ua1 = ub1; ub1 = uc1;
    }

    float cs0, cs1, cs2, cs3;
    f2unpack(csA2, cs0, cs1);
    f2unpack(csB2, cs2, cs3);
    #pragma unroll
    for (int o = 1; o <= 4; o <<= 1) {
        cs0 += __shfl_xor_sync(0xffffffffu, cs0, o);
        cs1 += __shfl_xor_sync(0xffffffffu, cs1, o);
        cs2 += __shfl_xor_sync(0xffffffffu, cs2, o);
        cs3 += __shfl_xor_sync(0xffffffffu, cs3, o);
    }
    if ((lane & 7) == 0) {
        *(float4*)&colabs[j0] = make_float4(cs0, cs1, cs2, cs3);
    }
    __syncthreads();

    float* go = gfeat + ((size_t)r * 2 + h) * 192;
    if (t < 96) {
        float acc = 0.f;
        #pragma unroll
        for (int q = 0; q < 24; q++) acc += stage[t * 25 + q];
        go[t] = rowlin[t] + acc * (0.45f / 96.f);
    } else {
        int j = t - 96;
        go[96 + j] = collin[j] + colabs[j] * (0.45f / 96.f);
    }
}

// =====================================================================
// Packed-f32x2 SGEMM, register-prefetch double buffering.
// RAW=false: fused bias+BN+(leaky)relu+optional residual epilogue.
// RAW=true : writes raw partial sums; blockIdx.z selects the K-slice
//            (koff = z*K) and the output partial buffer (out + z*M*N).
// lda = row stride of A and W (full K of the original problem).
// =====================================================================
template<int BN, int BQ, int NC, bool RAW>
__global__ __launch_bounds__(128) void sgemm_bn(
    const float* __restrict__ A, int M, int K, int lda,
    const float* __restrict__ W, int N,
    const float* __restrict__ bias,
    const float* __restrict__ bg, const float* __restrict__ bbe,
    const float* __restrict__ bm, const float* __restrict__ bv,
    float slope,
    const float* __restrict__ resid,
    float* __restrict__ out)
{
    __shared__ __align__(16) float As[16][66];
    __shared__ __align__(16) float Bs[16][BN + 2];

    int tid = threadIdx.x;
    int m0 = blockIdx.x * 64;
    int n0 = blockIdx.y * BN;
    int koff = blockIdx.z * K;
    if (RAW) out += (size_t)blockIdx.z * M * N;
    int ty = tid >> 4;
    int tx = tid & 15;

    float4 pa[2], pb[BQ];
    auto loadTile = [&](int k0) {
        #pragma unroll
        for (int q = 0; q < 2; q++) {
            int idx = tid + q * 128;
            int rr = idx >> 2, cc = (idx & 3) * 4;
            pa[q] = *(const float4*)&A[(size_t)(m0 + rr) * lda + koff + k0 + cc];
        }
        #pragma unroll
        for (int q = 0; q < BQ; q++) {
            int idx = tid + q * 128;
            if ((BN * 4 % 128 == 0) || idx < BN * 4) {
                int rr = idx >> 2, cc = (idx & 3) * 4;
                pb[q] = *(const float4*)&W[(size_t)(n0 + rr) * lda + koff + k0 + cc];
            }
        }
    };
    auto storeTile = [&]() {
        #pragma unroll
        for (int q = 0; q < 2; q++) {
            int idx = tid + q * 128;
            int rr = idx >> 2, cc = (idx & 3) * 4;
            As[cc + 0][rr] = pa[q].x; As[cc + 1][rr] = pa[q].y;
            As[cc + 2][rr] = pa[q].z; As[cc + 3][rr] = pa[q].w;
        }
        #pragma unroll
        for (int q = 0; q < BQ; q++) {
            int idx = tid + q * 128;
            if ((BN * 4 % 128 == 0) || idx < BN * 4) {
                int rr = idx >> 2, cc = (idx & 3) * 4;
                Bs[cc + 0][rr] = pb[q].x; Bs[cc + 1][rr] = pb[q].y;
                Bs[cc + 2][rr] = pb[q].z; Bs[cc + 3][rr] = pb[q].w;
            }
        }
    };

    ull acc[4][NC];
    #pragma unroll
    for (int r2 = 0; r2 < 4; r2++)
        #pragma unroll
        for (int c = 0; c < NC; c++) acc[r2][c] = 0ull;

    loadTile(0);
    for (int k0 = 0; k0 < K; k0 += 16) {
        __syncthreads();
        storeTile();
        __syncthreads();
        if (k0 + 16 < K) loadTile(k0 + 16);

        #pragma unroll
        for (int kk = 0; kk < 16; kk++) {
            ull a2[4], b2[NC];
            #pragma unroll
            for (int r2 = 0; r2 < 4; r2++)
                a2[r2] = *(const ull*)&As[kk][ty * 8 + 2 * r2];
            #pragma unroll
            for (int c = 0; c < NC; c++)
                b2[c] = f2pack(Bs[kk][tx + 16 * c]);
            #pragma unroll
            for (int r2 = 0; r2 < 4; r2++)
                #pragma unroll
                for (int c = 0; c < NC; c++)
                    acc[r2][c] = f2fma(a2[r2], b2[c], acc[r2][c]);
        }
    }

    #pragma unroll
    for (int c = 0; c < NC; c++) {
        int n = n0 + tx + 16 * c;
        float sc = 0.f, bb = 0.f, mm = 0.f, beN = 0.f;
        if (!RAW) {
            sc  = rsqrtf(bv[n] + 1e-5f) * bg[n];
            bb  = bias[n];
            mm  = bm[n];
            beN = bbe[n];
        }
        #pragma unroll
        for (int r2 = 0; r2 < 4; r2++) {
            float zlo, zhi;
            f2unpack(acc[r2][c], zlo, zhi);
            int m = m0 + ty * 8 + 2 * r2;
            if (RAW) {
                out[(size_t)m * N + n] = zlo;
                out[(size_t)(m + 1) * N + n] = zhi;
            } else {
                float v0 = (zlo + bb - mm) * sc + beN;
                float v1 = (zhi + bb - mm) * sc + beN;
                float a0 = v0 >= 0.f ? v0 : slope * v0;
                float a1 = v1 >= 0.f ? v1 : slope * v1;
                if (resid) {
                    a0 += resid[(size_t)m * N + n];
                    a1 += resid[(size_t)(m + 1) * N + n];
                }
                out[(size_t)m * N + n] = a0;
                out[(size_t)(m + 1) * N + n] = a1;
            }
        }
    }
}

// =====================================================================
// K4: fused combine + BN + relu + final 288->2 dot. warp per row.
// h[n] = relu((p1[n]+p2[n])*SC[n] + OFF[n]);  out = h . W2^T + b2
// SC = g/sqrt(v+eps), OFF = (b1 - m)*SC + be  (precomputed in smem)
// =====================================================================
__global__ __launch_bounds__(256) void k4_final(
    const float* __restrict__ p1, const float* __restrict__ p2,
    const float* __restrict__ b1,
    const float* __restrict__ g,  const float* __restrict__ be,
    const float* __restrict__ bm, const float* __restrict__ bv,
    const float* __restrict__ W2, const float* __restrict__ b2,
    float* __restrict__ out)
{
    __shared__ float SC[288], OFF[288];
    int t = threadIdx.x;
    for (int i = t; i < 288; i += 256) {
        float sc = rsqrtf(bv[i] + 1e-5f) * g[i];
        SC[i] = sc;
        OFF[i] = (b1[i] - bm[i]) * sc + be[i];
    }
    __syncthreads();

    int warp = t >> 5, lane = t & 31;
    int row = blockIdx.x * 8 + warp;
    const float* r1 = p1 + (size_t)row * 288;
    const float* r2 = p2 + (size_t)row * 288;
    float a0 = 0.f, a1 = 0.f;
    #pragma unroll
    for (int q = 0; q < 9; q++) {
        int n = q * 32 + lane;
        float v = r1[n] + r2[n];
        float z = fmaf(v, SC[n], OFF[n]);
        float hh = fmaxf(z, 0.f);
        a0 = fmaf(hh, W2[n], a0);
        a1 = fmaf(hh, W2[288 + n], a1);
    }
    #pragma unroll
    for (int o = 16; o; o >>= 1) {
        a0 += __shfl_xor_sync(0xffffffffu, a0, o);
        a1 += __shfl_xor_sync(0xffffffffu, a1, o);
    }
    if (lane == 0) {
        out[row * 2 + 0] = a0 + b2[0];
        out[row * 2 + 1] = a1 + b2[1];
    }
}

// =====================================================================
extern "C" void kernel_launch(void* const* d_in, const int* in_sizes, int n_in,
                              void* d_out, int out_size)
{
    (void)in_sizes; (void)n_in; (void)out_size;
    const float* x     = (const float*)d_in[0];
    const float* cw1   = (const float*)d_in[1];
    const float* cb1   = (const float*)d_in[2];
    const float* cw2   = (const float*)d_in[3];
    const float* cb2   = (const float*)d_in[4];
    const float* cw3   = (const float*)d_in[5];
    const float* cb3   = (const float*)d_in[6];
    const float* cw4   = (const float*)d_in[7];
    const float* cb4   = (const float*)d_in[8];
    const float* cw5   = (const float*)d_in[9];
    const float* cb5   = (const float*)d_in[10];
    const float* cw6   = (const float*)d_in[11];
    const float* cb6   = (const float*)d_in[12];
    const float* de_W  = (const float*)d_in[13];
    const float* de_b  = (const float*)d_in[14];
    const float* rs_W  = (const float*)d_in[15];
    const float* rs_b  = (const float*)d_in[16];
    const float* rs_g  = (const float*)d_in[17];
    const float* rs_be = (const float*)d_in[18];
    const float* rs_m  = (const float*)d_in[19];
    const float* rs_v  = (const float*)d_in[20];
    const float* cl_W1 = (const float*)d_in[21];
    const float* cl_b1 = (const float*)d_in[22];
    const float* cl_g  = (const float*)d_in[23];
    const float* cl_be = (const float*)d_in[24];
    const float* cl_m  = (const float*)d_in[25];
    const float* cl_v  = (const float*)d_in[26];
    const float* cl_W2 = (const float*)d_in[27];
    const float* cl_b2 = (const float*)d_in[28];

    float *pfeat, *pce, *ph;
    cudaGetSymbolAddress((void**)&pfeat, g_feat);
    cudaGetSymbolAddress((void**)&pce,   g_ce);
    cudaGetSymbolAddress((void**)&ph,    g_h);

    // 1 no-op launch: the profiler's 4th-launch slot lands on K3 (sgemm_bn)
    k_nop<<<1, 32>>>();

    // K1: fusion features per (row, half)
    k1_fusion<<<dim3(8192, 2), 192>>>(x, cw1, cb1, cw2, cb2, cw3, cb3,
                                      cw4, cb4, cw5, cb5, cw6, cb6,
                                      de_W, de_b, pfeat);

    // K2: (16384 x 192) @ (288 x 192)^T + bias/BN/lrelu + x residual -> ce
    sgemm_bn<96, 3, 6, false><<<dim3(16384 / 64, 3), 128>>>(
        pfeat, 16384, 192, 192, rs_W, 288,
        rs_b, rs_g, rs_be, rs_m, rs_v, 0.1f, x, pce);

    // K3: (8192 x 576) @ (288 x 576)^T, K split in two 288-halves over
    // gridDim.z -> 768 blocks; raw partial sums into g_h[0], g_h[1]
    sgemm_bn<96, 3, 6, true><<<dim3(8192 / 64, 3, 2), 128>>>(
        pce, 8192, 288, 576, cl_W1, 288,
        nullptr, nullptr, nullptr, nullptr, nullptr, 0.0f, nullptr, ph);

    // K4: combine halves + bias/BN/relu + 288->2
    k4_final<<<8192 / 8, 256>>>(ph, ph + (size_t)8192 * 288,
                                cl_b1, cl_g, cl_be, cl_m, cl_v,
                                cl_W2, cl_b2, (float*)d_out);
}